// round 1
// baseline (speedup 1.0000x reference)
#include <cuda_runtime.h>
#include <math.h>

// ---------------- problem constants ----------------
#define BSZ   256
#define WINS  20
#define H1S   12          // conv1 output side
#define P1    144         // 12*12
#define P2    16          // 4*4
#define RTS   512
#define NCP   10
#define DOUTC 16
#define DINC  8
#define K1    81
#define K2    20736       // 256*81
#define M1    (BSZ*P1)    // 36864
#define M2    (BSZ*P2)    // 4096
#define RECS  102400
#define DEC1  512
#define DEC2  1024

// ---------------- scratch (static device globals; no allocation) ----------------
__device__ float g_A1[M1 * K1];            // im2col of data
__device__ float g_C1[M1 * 256];           // conv1 output, [(b,pos), c]
__device__ float g_W2p[256 * K2];          // prim_w permuted to k=(rr*256+c)
__device__ float g_A2[(size_t)M2 * K2];    // im2col for primary caps (340MB)
__device__ float g_U [M2 * 256];           // primary caps pre-squash [(b,p), o]
__device__ float g_X [BSZ * RTS * DINC];   // squashed routes
__device__ float g_UH[(size_t)BSZ * RTS * 160]; // u_hat [b][r][c*16+o] (84MB)
__device__ float g_BIJ[RTS * NCP];
__device__ float g_CIJ[RTS * NCP];
__device__ float g_V [BSZ * 160];
__device__ int   g_IDX[BSZ];
__device__ float g_H1[BSZ * DEC1];
__device__ float g_H2[BSZ * DEC2];

// ---------------- im2col for conv1 ----------------
__global__ void im2col1_kernel(const float* __restrict__ data) {
    int idx = blockIdx.x * blockDim.x + threadIdx.x;
    if (idx >= M1 * K1) return;
    int m  = idx / K1, kk = idx % K1;
    int b  = m / P1,  pos = m % P1;
    int y  = pos / H1S, x = pos % H1S;
    int ky = kk / 9,  kx = kk % 9;
    g_A1[idx] = data[(size_t)b * 400 + (y + ky) * 20 + (x + kx)];
}

// ---------------- permute prim_w: W2p[o][rr*256+c] = prim_w[o][c][rr] ----------------
__global__ void permute_w2_kernel(const float* __restrict__ prim_w) {
    int idx = blockIdx.x * blockDim.x + threadIdx.x;
    if (idx >= 256 * K2) return;
    int o   = idx / K2;
    int rem = idx % K2;
    int rr  = rem >> 8;      // 0..80
    int c   = rem & 255;
    g_W2p[idx] = prim_w[(size_t)o * K2 + c * 81 + rr];
}

// ---------------- im2col for primary caps (k = rr*256 + c, coalesced both sides) ----------------
__global__ void im2col2_kernel() {
    int idx = blockIdx.x * blockDim.x + threadIdx.x;
    if (idx >= (int)(M2 * (long long)K2 > 0 ? 0 : 0)) {} // (kept trivially false)
    long long gid = (long long)blockIdx.x * blockDim.x + threadIdx.x;
    if (gid >= (long long)M2 * K2) return;
    int m   = (int)(gid / K2);
    int rem = (int)(gid % K2);
    int rr  = rem >> 8;
    int c   = rem & 255;
    int b = m >> 4, p = m & 15;
    int Y = p >> 2, X = p & 3;
    int ky = rr / 9, kx = rr % 9;
    g_A2[(size_t)gid] = g_C1[(size_t)(b * P1 + (Y + ky) * H1S + (X + kx)) * 256 + c];
}

// ---------------- generic NT SGEMM: C[M,N] = act(A[M,K] * W[N,K]^T + bias) ----------------
// BM=128, BN=64, BK=16, 256 threads, 8x4 per-thread tile. Requires M%128==0, N%64==0.
template<int ACT>
__global__ __launch_bounds__(256)
void gemm_nt(const float* __restrict__ A, const float* __restrict__ W,
             const float* __restrict__ bias, float* __restrict__ C,
             int M, int N, int K) {
    constexpr int BM = 128, BN = 64, BK = 16;
    __shared__ float AsT[BK][BM + 4];
    __shared__ float BsT[BK][BN + 4];

    const int t  = threadIdx.x;
    const int m0 = blockIdx.x * BM;
    const int n0 = blockIdx.y * BN;
    const int trow = t >> 4;   // 0..15
    const int tcol = t & 15;   // 0..15
    const bool k4 = ((K & 3) == 0);

    float acc[8][4];
#pragma unroll
    for (int i = 0; i < 8; i++)
#pragma unroll
        for (int j = 0; j < 4; j++) acc[i][j] = 0.f;

    for (int k0 = 0; k0 < K; k0 += BK) {
        // load A tile: 128x16 -> 512 float4, 2 per thread
#pragma unroll
        for (int qq = 0; qq < 2; qq++) {
            int q = t + qq * 256;
            int row = q >> 2, kseg = q & 3;
            int kb = k0 + kseg * 4;
            float4 va;
            if (k4 && kb + 3 < K) {
                va = *reinterpret_cast<const float4*>(&A[(size_t)(m0 + row) * K + kb]);
            } else {
                const float* ap = &A[(size_t)(m0 + row) * K];
                va.x = (kb + 0 < K) ? ap[kb + 0] : 0.f;
                va.y = (kb + 1 < K) ? ap[kb + 1] : 0.f;
                va.z = (kb + 2 < K) ? ap[kb + 2] : 0.f;
                va.w = (kb + 3 < K) ? ap[kb + 3] : 0.f;
            }
            AsT[kseg * 4 + 0][row] = va.x;
            AsT[kseg * 4 + 1][row] = va.y;
            AsT[kseg * 4 + 2][row] = va.z;
            AsT[kseg * 4 + 3][row] = va.w;
        }
        // load W tile: 64x16 -> 256 float4, 1 per thread
        {
            int row = t >> 2, kseg = t & 3;
            int kb = k0 + kseg * 4;
            float4 vb;
            if (k4 && kb + 3 < K) {
                vb = *reinterpret_cast<const float4*>(&W[(size_t)(n0 + row) * K + kb]);
            } else {
                const float* wp = &W[(size_t)(n0 + row) * K];
                vb.x = (kb + 0 < K) ? wp[kb + 0] : 0.f;
                vb.y = (kb + 1 < K) ? wp[kb + 1] : 0.f;
                vb.z = (kb + 2 < K) ? wp[kb + 2] : 0.f;
                vb.w = (kb + 3 < K) ? wp[kb + 3] : 0.f;
            }
            BsT[kseg * 4 + 0][row] = vb.x;
            BsT[kseg * 4 + 1][row] = vb.y;
            BsT[kseg * 4 + 2][row] = vb.z;
            BsT[kseg * 4 + 3][row] = vb.w;
        }
        __syncthreads();
#pragma unroll
        for (int kk = 0; kk < BK; kk++) {
            float a[8], b[4];
            *reinterpret_cast<float4*>(&a[0]) = *reinterpret_cast<const float4*>(&AsT[kk][trow * 8]);
            *reinterpret_cast<float4*>(&a[4]) = *reinterpret_cast<const float4*>(&AsT[kk][trow * 8 + 4]);
            *reinterpret_cast<float4*>(&b[0]) = *reinterpret_cast<const float4*>(&BsT[kk][tcol * 4]);
#pragma unroll
            for (int i = 0; i < 8; i++)
#pragma unroll
                for (int j = 0; j < 4; j++) acc[i][j] = fmaf(a[i], b[j], acc[i][j]);
        }
        __syncthreads();
    }

    float4 bv = *reinterpret_cast<const float4*>(&bias[n0 + tcol * 4]);
#pragma unroll
    for (int i = 0; i < 8; i++) {
        int m = m0 + trow * 8 + i;
        float4 out;
        out.x = acc[i][0] + bv.x;
        out.y = acc[i][1] + bv.y;
        out.z = acc[i][2] + bv.z;
        out.w = acc[i][3] + bv.w;
        if (ACT == 1) {
            out.x = fmaxf(out.x, 0.f); out.y = fmaxf(out.y, 0.f);
            out.z = fmaxf(out.z, 0.f); out.w = fmaxf(out.w, 0.f);
        } else if (ACT == 2) {
            out.x = 1.f / (1.f + expf(-out.x));
            out.y = 1.f / (1.f + expf(-out.y));
            out.z = 1.f / (1.f + expf(-out.z));
            out.w = 1.f / (1.f + expf(-out.w));
        }
        *reinterpret_cast<float4*>(&C[(size_t)m * N + n0 + tcol * 4]) = out;
    }
}

// ---------------- squash primary caps into route vectors ----------------
// route r = o*2 + (p/8), i = p%8 ;  U layout [(b*16+p), o]
__global__ void squash_kernel() {
    int t = blockIdx.x * blockDim.x + threadIdx.x;
    if (t >= BSZ * RTS) return;
    int b = t / RTS, r = t % RTS;
    int o = r >> 1, hi = r & 1;
    const float* up = &g_U[(size_t)(b * 16 + hi * 8) * 256 + o];
    float u[8], sn = 0.f;
#pragma unroll
    for (int i = 0; i < 8; i++) { u[i] = up[(size_t)i * 256]; sn += u[i] * u[i]; }
    float sc = sn / ((1.f + sn) * sqrtf(sn));
#pragma unroll
    for (int i = 0; i < 8; i++) g_X[(size_t)t * 8 + i] = u[i] * sc;
}

// ---------------- u_hat[b,r,c,o] = sum_i W[r,c,o,i] * x[b,r,i] ----------------
__global__ void uhat_kernel(const float* __restrict__ Wd) {
    int r = blockIdx.x;       // 512
    int t = threadIdx.x;      // 160 threads: t = c*16+o
    __shared__ float Wr[1280];
    __shared__ float Xr[2048];
    for (int q = t; q < 1280; q += 160) Wr[q] = Wd[(size_t)r * 1280 + q];
    for (int q = t; q < 2048; q += 160) {
        int b = q >> 3, i = q & 7;
        Xr[q] = g_X[(size_t)(b * RTS + r) * 8 + i];
    }
    __syncthreads();
    for (int b = 0; b < BSZ; b++) {
        float acc = 0.f;
#pragma unroll
        for (int i = 0; i < 8; i++) acc = fmaf(Wr[t * 8 + i], Xr[b * 8 + i], acc);
        g_UH[(size_t)(b * RTS + r) * 160 + t] = acc;
    }
}

__global__ void zero_bij_kernel() {
    int t = blockIdx.x * blockDim.x + threadIdx.x;
    if (t < RTS * NCP) g_BIJ[t] = 0.f;
}

// ---------------- softmax over routes (axis 0 of [512,10]) ----------------
__global__ void softmax_routes_kernel() {
    __shared__ float sm[RTS * NCP];
    __shared__ float mx[NCP], sum[NCP];
    int t = threadIdx.x; // 512
    for (int q = t; q < RTS * NCP; q += 512) sm[q] = g_BIJ[q];
    __syncthreads();
    if (t < NCP) {
        float m = -1e30f;
        for (int r = 0; r < RTS; r++) m = fmaxf(m, sm[r * NCP + t]);
        float s = 0.f;
        for (int r = 0; r < RTS; r++) s += expf(sm[r * NCP + t] - m);
        mx[t] = m; sum[t] = s;
    }
    __syncthreads();
    for (int q = t; q < RTS * NCP; q += 512) {
        int j = q % NCP;
        g_CIJ[q] = expf(sm[q] - mx[j]) / sum[j];
    }
}

// ---------------- s = sum_r c[r,j]*u_hat ; v = elementwise squash ----------------
__global__ void route_sv_kernel() {
    int b = blockIdx.x;   // 256
    int t = threadIdx.x;  // 160, t = j*16+o
    __shared__ float cs[RTS * NCP];
    for (int q = t; q < RTS * NCP; q += 160) cs[q] = g_CIJ[q];
    __syncthreads();
    int j = t >> 4;
    const float* uh = &g_UH[(size_t)b * RTS * 160 + t];
    float acc = 0.f;
    for (int r = 0; r < RTS; r++) acc = fmaf(cs[r * NCP + j], uh[(size_t)r * 160], acc);
    float sq = acc * acc;
    float v = sq * acc / ((1.f + sq) * sqrtf(sq));
    g_V[b * 160 + t] = v;
}

// ---------------- agreement: b_ij += mean_b sum_o u_hat*v (deterministic) ----------------
__global__ void route_agree_kernel() {
    int r = blockIdx.x;   // 512
    int b = threadIdx.x;  // 256
    __shared__ float red[256][NCP];
    const float4* up = reinterpret_cast<const float4*>(&g_UH[(size_t)(b * RTS + r) * 160]);
    const float4* vp = reinterpret_cast<const float4*>(&g_V[b * 160]);
    float dj[NCP];
#pragma unroll
    for (int j = 0; j < NCP; j++) dj[j] = 0.f;
#pragma unroll
    for (int q = 0; q < 40; q++) {
        float4 u4 = up[q];
        float4 v4 = vp[q];
        int j = q >> 2;
        dj[j] += u4.x * v4.x + u4.y * v4.y + u4.z * v4.z + u4.w * v4.w;
    }
#pragma unroll
    for (int j = 0; j < NCP; j++) red[b][j] = dj[j];
    __syncthreads();
    if (b < NCP) {
        float s = 0.f;
        for (int q = 0; q < 256; q++) s += red[q][b];
        g_BIJ[r * NCP + b] += s * (1.f / 256.f);
    }
}

// ---------------- classes: norm, legacy softmax over batch axis, argmax ----------------
__global__ void classes_argmax_kernel() {
    int b = threadIdx.x; // 256
    __shared__ float cl[256 * NCP];
    __shared__ float lz[NCP];
    for (int j = 0; j < NCP; j++) {
        float s = 0.f;
        for (int o = 0; o < DOUTC; o++) {
            float v = g_V[b * 160 + j * 16 + o];
            s += v * v;
        }
        cl[b * NCP + j] = sqrtf(s);
    }
    __syncthreads();
    if (b < NCP) {
        float m = -1e30f;
        for (int q = 0; q < 256; q++) m = fmaxf(m, cl[q * NCP + b]);
        float s = 0.f;
        for (int q = 0; q < 256; q++) s += expf(cl[q * NCP + b] - m);
        lz[b] = m + logf(s);
    }
    __syncthreads();
    int best = 0;
    float bv = cl[b * NCP + 0] - lz[0];
    for (int j = 1; j < NCP; j++) {
        float v = cl[b * NCP + j] - lz[j];
        if (v > bv) { bv = v; best = j; }
    }
    g_IDX[b] = best;
}

// ---------------- decoder layer 1 (sparse: only 16 nonzero inputs) ----------------
__global__ void dec1_kernel(const float* __restrict__ w1, const float* __restrict__ b1) {
    int b = blockIdx.x;    // 256
    int k = threadIdx.x;   // 512
    __shared__ float vs[16];
    __shared__ int idx;
    if (k == 0) idx = g_IDX[b];
    __syncthreads();
    if (k < 16) vs[k] = g_V[b * 160 + idx * 16 + k];
    __syncthreads();
    float acc = b1[k];
    const float* wp = &w1[(size_t)k * 160 + idx * 16];
#pragma unroll
    for (int o = 0; o < 16; o++) acc = fmaf(vs[o], wp[o], acc);
    g_H1[b * DEC1 + k] = fmaxf(acc, 0.f);
}

// ---------------- launch ----------------
extern "C" void kernel_launch(void* const* d_in, const int* in_sizes, int n_in,
                              void* d_out, int out_size) {
    const float* data    = (const float*)d_in[0];
    const float* conv1_w = (const float*)d_in[1];
    const float* conv1_b = (const float*)d_in[2];
    const float* prim_w  = (const float*)d_in[3];
    const float* prim_b  = (const float*)d_in[4];
    const float* W_digit = (const float*)d_in[5];
    const float* dec_w1  = (const float*)d_in[6];
    const float* dec_b1  = (const float*)d_in[7];
    const float* dec_w2  = (const float*)d_in[8];
    const float* dec_b2  = (const float*)d_in[9];
    const float* dec_w3  = (const float*)d_in[10];
    const float* dec_b3  = (const float*)d_in[11];
    float* out = (float*)d_out;

    float *pA1, *pC1, *pW2p, *pA2, *pU, *pH1, *pH2;
    cudaGetSymbolAddress((void**)&pA1,  g_A1);
    cudaGetSymbolAddress((void**)&pC1,  g_C1);
    cudaGetSymbolAddress((void**)&pW2p, g_W2p);
    cudaGetSymbolAddress((void**)&pA2,  g_A2);
    cudaGetSymbolAddress((void**)&pU,   g_U);
    cudaGetSymbolAddress((void**)&pH1,  g_H1);
    cudaGetSymbolAddress((void**)&pH2,  g_H2);

    // 1) conv1 as GEMM
    im2col1_kernel<<<(M1 * K1 + 255) / 256, 256>>>(data);
    gemm_nt<1><<<dim3(M1 / 128, 256 / 64), 256>>>(pA1, conv1_w, conv1_b, pC1, M1, 256, K1);

    // 2) primary caps conv as GEMM (permuted-K im2col)
    permute_w2_kernel<<<(256 * K2 + 255) / 256, 256>>>(prim_w);
    im2col2_kernel<<<(unsigned)(((long long)M2 * K2 + 255) / 256), 256>>>();
    gemm_nt<0><<<dim3(M2 / 128, 256 / 64), 256>>>(pA2, pW2p, prim_b, pU, M2, 256, K2);

    // 3) squash + u_hat
    squash_kernel<<<(BSZ * RTS + 255) / 256, 256>>>();
    uhat_kernel<<<RTS, 160>>>(W_digit);

    // 4) dynamic routing (3 iterations, b_ij shared over batch)
    zero_bij_kernel<<<(RTS * NCP + 255) / 256, 256>>>();
    for (int it = 0; it < 3; it++) {
        softmax_routes_kernel<<<1, 512>>>();
        route_sv_kernel<<<BSZ, 160>>>();
        if (it < 2) route_agree_kernel<<<RTS, 256>>>();
    }

    // 5) classes / mask / decoder
    classes_argmax_kernel<<<1, 256>>>();
    dec1_kernel<<<BSZ, DEC1>>>(dec_w1, dec_b1);
    gemm_nt<1><<<dim3(BSZ / 128, DEC2 / 64), 256>>>(pH1, dec_w2, dec_b2, pH2, BSZ, DEC2, DEC1);
    gemm_nt<2><<<dim3(BSZ / 128, RECS / 64), 256>>>(pH2, dec_w3, dec_b3, out, BSZ, RECS, DEC2);
}

// round 2
// speedup vs baseline: 1.0599x; 1.0599x over previous
#include <cuda_runtime.h>
#include <math.h>

// ---------------- problem constants ----------------
#define BSZ   256
#define H1S   12          // conv1 output side
#define P1    144         // 12*12
#define P2    16          // 4*4
#define RTS   512
#define NCP   10
#define DOUTC 16
#define K1P   96          // conv1 K padded 81 -> 96
#define K2    20736       // 256*81
#define M1    (BSZ*P1)    // 36864
#define M2    (BSZ*P2)    // 4096
#define RECS  102400
#define DEC1  512
#define DEC2  1024

// ---------------- scratch (static device globals; no allocation) ----------------
__device__ float g_A1[M1 * K1P];           // padded im2col of data (14MB)
__device__ float g_W1p[256 * K1P];         // padded conv1 weights
__device__ float g_C1[M1 * 256];           // conv1 output, [(b,pos), c] (38MB, L2-resident)
__device__ float g_W2p[256 * K2];          // prim_w permuted to k=(rr*256+c)
__device__ float g_U [M2 * 256];           // primary caps pre-squash [(b,p), o]
__device__ float g_X [BSZ * RTS * 8];      // squashed routes
__device__ float g_UH[(size_t)BSZ * RTS * 160]; // u_hat [b][r][c*16+o] (84MB)
__device__ float g_BIJ[RTS * NCP];
__device__ float g_CIJ[RTS * NCP];
__device__ float g_V [BSZ * 160];
__device__ int   g_IDX[BSZ];
__device__ float g_H1[BSZ * DEC1];
__device__ float g_H2[BSZ * DEC2];

// ---------------- f32x2 helpers ----------------
__device__ __forceinline__ void fma2(unsigned long long& d, unsigned long long a, unsigned long long b) {
    asm("fma.rn.f32x2 %0, %1, %2, %0;" : "+l"(d) : "l"(a), "l"(b));
}
__device__ __forceinline__ unsigned long long dup2u(float x) {
    unsigned long long r;
    unsigned int xi = __float_as_uint(x);
    asm("mov.b64 %0, {%1, %1};" : "=l"(r) : "r"(xi));
    return r;
}
__device__ __forceinline__ float2 up2(unsigned long long v) {
    float2 f;
    asm("mov.b64 {%0, %1}, %2;" : "=f"(f.x), "=f"(f.y) : "l"(v));
    return f;
}

// ---------------- im2col for conv1 (K padded to 96 with zeros) ----------------
__global__ void im2col1_kernel(const float* __restrict__ data) {
    int idx = blockIdx.x * blockDim.x + threadIdx.x;
    if (idx >= M1 * K1P) return;
    int m  = idx / K1P, kk = idx % K1P;
    float v = 0.f;
    if (kk < 81) {
        int b  = m / P1,  pos = m % P1;
        int y  = pos / H1S, x = pos % H1S;
        int ky = kk / 9,  kx = kk % 9;
        v = data[(size_t)b * 400 + (y + ky) * 20 + (x + kx)];
    }
    g_A1[idx] = v;
}

// ---------------- pad conv1 weights to K=96 ----------------
__global__ void permute_w1_kernel(const float* __restrict__ conv1_w) {
    int idx = blockIdx.x * blockDim.x + threadIdx.x;
    if (idx >= 256 * K1P) return;
    int o = idx / K1P, kk = idx % K1P;
    g_W1p[idx] = (kk < 81) ? conv1_w[o * 81 + kk] : 0.f;
}

// ---------------- permute prim_w: W2p[o][rr*256+c] = prim_w[o][c][rr] ----------------
__global__ void permute_w2_kernel(const float* __restrict__ prim_w) {
    int idx = blockIdx.x * blockDim.x + threadIdx.x;
    if (idx >= 256 * K2) return;
    int o   = idx / K2;
    int rem = idx % K2;
    int rr  = rem >> 8;      // 0..80
    int c   = rem & 255;
    g_W2p[idx] = prim_w[(size_t)o * K2 + c * 81 + rr];
}

// ---------------- NT SGEMM with packed f32x2 FMAs ----------------
// C[M,N] = act(A[M,K] * W[N,K]^T + bias). BM=128,BN=64,BK=16, 256 thr, 8x4/thread.
// MODE 0: A read directly (K%16==0, rows 16B aligned).
// MODE 1: implicit im2col from g_C1 (prim caps): k=(rr*256+c), A arg = g_C1.
template<int ACT, int MODE>
__global__ __launch_bounds__(256, 2)
void gemm_nt2(const float* __restrict__ A, const float* __restrict__ W,
              const float* __restrict__ bias, float* __restrict__ C,
              int M, int N, int K) {
    constexpr int BM = 128, BN = 64, BK = 16;
    __shared__ float As2[BK][2 * BM + 8];   // duplicated pairs {a,a}
    __shared__ float Bs [BK][BN + 8];

    const int t  = threadIdx.x;
    const int m0 = blockIdx.x * BM;
    const int n0 = blockIdx.y * BN;
    const int trow = t >> 4;   // 0..15
    const int tcol = t & 15;   // 0..15

    // implicit-mode row bases (conv output row index sans kernel offset)
    int mbase[2] = {0, 0};
    if (MODE == 1) {
#pragma unroll
        for (int qq = 0; qq < 2; qq++) {
            int row = (t + qq * 256) >> 2;
            int m = m0 + row;
            int b = m >> 4, p = m & 15;
            mbase[qq] = b * 144 + (p >> 2) * 12 + (p & 3);
        }
    }

    unsigned long long acc[8][2];
#pragma unroll
    for (int i = 0; i < 8; i++) { acc[i][0] = 0ull; acc[i][1] = 0ull; }

    for (int k0 = 0; k0 < K; k0 += BK) {
        // ---- load A tile (duplicated into As2) ----
        if (MODE == 0) {
#pragma unroll
            for (int qq = 0; qq < 2; qq++) {
                int q = t + qq * 256;
                int row = q >> 2, kseg = q & 3;
                float4 va = *reinterpret_cast<const float4*>(&A[(size_t)(m0 + row) * K + k0 + kseg * 4]);
                *reinterpret_cast<unsigned long long*>(&As2[kseg * 4 + 0][2 * row]) = dup2u(va.x);
                *reinterpret_cast<unsigned long long*>(&As2[kseg * 4 + 1][2 * row]) = dup2u(va.y);
                *reinterpret_cast<unsigned long long*>(&As2[kseg * 4 + 2][2 * row]) = dup2u(va.z);
                *reinterpret_cast<unsigned long long*>(&As2[kseg * 4 + 3][2 * row]) = dup2u(va.w);
            }
        } else {
            int rr = k0 >> 8;               // constant across BK (256%16==0)
            int c0 = k0 & 255;
            int off = (rr / 9) * 12 + (rr % 9);
#pragma unroll
            for (int qq = 0; qq < 2; qq++) {
                int q = t + qq * 256;
                int row = q >> 2, kseg = q & 3;
                int c1row = mbase[qq] + off;
                float4 va = *reinterpret_cast<const float4*>(&A[(size_t)c1row * 256 + c0 + kseg * 4]);
                *reinterpret_cast<unsigned long long*>(&As2[kseg * 4 + 0][2 * row]) = dup2u(va.x);
                *reinterpret_cast<unsigned long long*>(&As2[kseg * 4 + 1][2 * row]) = dup2u(va.y);
                *reinterpret_cast<unsigned long long*>(&As2[kseg * 4 + 2][2 * row]) = dup2u(va.z);
                *reinterpret_cast<unsigned long long*>(&As2[kseg * 4 + 3][2 * row]) = dup2u(va.w);
            }
        }
        // ---- load W tile: 64x16 -> 256 float4, 1 per thread ----
        {
            int row = t >> 2, kseg = t & 3;
            float4 vb = *reinterpret_cast<const float4*>(&W[(size_t)(n0 + row) * K + k0 + kseg * 4]);
            Bs[kseg * 4 + 0][row] = vb.x;
            Bs[kseg * 4 + 1][row] = vb.y;
            Bs[kseg * 4 + 2][row] = vb.z;
            Bs[kseg * 4 + 3][row] = vb.w;
        }
        __syncthreads();
#pragma unroll
        for (int kk = 0; kk < BK; kk++) {
            ulonglong2 a01 = *reinterpret_cast<const ulonglong2*>(&As2[kk][trow * 16 + 0]);
            ulonglong2 a23 = *reinterpret_cast<const ulonglong2*>(&As2[kk][trow * 16 + 4]);
            ulonglong2 a45 = *reinterpret_cast<const ulonglong2*>(&As2[kk][trow * 16 + 8]);
            ulonglong2 a67 = *reinterpret_cast<const ulonglong2*>(&As2[kk][trow * 16 + 12]);
            ulonglong2 b01 = *reinterpret_cast<const ulonglong2*>(&Bs[kk][tcol * 4]);
            fma2(acc[0][0], a01.x, b01.x); fma2(acc[0][1], a01.x, b01.y);
            fma2(acc[1][0], a01.y, b01.x); fma2(acc[1][1], a01.y, b01.y);
            fma2(acc[2][0], a23.x, b01.x); fma2(acc[2][1], a23.x, b01.y);
            fma2(acc[3][0], a23.y, b01.x); fma2(acc[3][1], a23.y, b01.y);
            fma2(acc[4][0], a45.x, b01.x); fma2(acc[4][1], a45.x, b01.y);
            fma2(acc[5][0], a45.y, b01.x); fma2(acc[5][1], a45.y, b01.y);
            fma2(acc[6][0], a67.x, b01.x); fma2(acc[6][1], a67.x, b01.y);
            fma2(acc[7][0], a67.y, b01.x); fma2(acc[7][1], a67.y, b01.y);
        }
        __syncthreads();
    }

    float4 bv = *reinterpret_cast<const float4*>(&bias[n0 + tcol * 4]);
#pragma unroll
    for (int i = 0; i < 8; i++) {
        int m = m0 + trow * 8 + i;
        float2 p0 = up2(acc[i][0]);
        float2 p1 = up2(acc[i][1]);
        float4 out;
        out.x = p0.x + bv.x;
        out.y = p0.y + bv.y;
        out.z = p1.x + bv.z;
        out.w = p1.y + bv.w;
        if (ACT == 1) {
            out.x = fmaxf(out.x, 0.f); out.y = fmaxf(out.y, 0.f);
            out.z = fmaxf(out.z, 0.f); out.w = fmaxf(out.w, 0.f);
        } else if (ACT == 2) {
            out.x = 1.f / (1.f + expf(-out.x));
            out.y = 1.f / (1.f + expf(-out.y));
            out.z = 1.f / (1.f + expf(-out.z));
            out.w = 1.f / (1.f + expf(-out.w));
        }
        *reinterpret_cast<float4*>(&C[(size_t)m * N + n0 + tcol * 4]) = out;
    }
}

// ---------------- squash primary caps into route vectors ----------------
__global__ void squash_kernel() {
    int t = blockIdx.x * blockDim.x + threadIdx.x;
    if (t >= BSZ * RTS) return;
    int b = t / RTS, r = t % RTS;
    int o = r >> 1, hi = r & 1;
    const float* up = &g_U[(size_t)(b * 16 + hi * 8) * 256 + o];
    float u[8], sn = 0.f;
#pragma unroll
    for (int i = 0; i < 8; i++) { u[i] = up[(size_t)i * 256]; sn += u[i] * u[i]; }
    float sc = sn / ((1.f + sn) * sqrtf(sn));
#pragma unroll
    for (int i = 0; i < 8; i++) g_X[(size_t)t * 8 + i] = u[i] * sc;
}

// ---------------- u_hat[b,r,c,o] = sum_i W[r,c,o,i] * x[b,r,i] ----------------
__global__ void uhat_kernel(const float* __restrict__ Wd) {
    int r = blockIdx.x;       // 512
    int t = threadIdx.x;      // 160 threads: t = c*16+o
    __shared__ float Wr[1280];
    __shared__ float Xr[2048];
    for (int q = t; q < 1280; q += 160) Wr[q] = Wd[(size_t)r * 1280 + q];
    for (int q = t; q < 2048; q += 160) {
        int b = q >> 3, i = q & 7;
        Xr[q] = g_X[(size_t)(b * RTS + r) * 8 + i];
    }
    __syncthreads();
    for (int b = 0; b < BSZ; b++) {
        float acc = 0.f;
#pragma unroll
        for (int i = 0; i < 8; i++) acc = fmaf(Wr[t * 8 + i], Xr[b * 8 + i], acc);
        g_UH[(size_t)(b * RTS + r) * 160 + t] = acc;
    }
}

__global__ void zero_bij_kernel() {
    int t = blockIdx.x * blockDim.x + threadIdx.x;
    if (t < RTS * NCP) g_BIJ[t] = 0.f;
}

// ---------------- softmax over routes (axis 0 of [512,10]) ----------------
__global__ void softmax_routes_kernel() {
    __shared__ float sm[RTS * NCP];
    __shared__ float mx[NCP], sum[NCP];
    int t = threadIdx.x; // 512
    for (int q = t; q < RTS * NCP; q += 512) sm[q] = g_BIJ[q];
    __syncthreads();
    if (t < NCP) {
        float m = -1e30f;
        for (int r = 0; r < RTS; r++) m = fmaxf(m, sm[r * NCP + t]);
        float s = 0.f;
        for (int r = 0; r < RTS; r++) s += expf(sm[r * NCP + t] - m);
        mx[t] = m; sum[t] = s;
    }
    __syncthreads();
    for (int q = t; q < RTS * NCP; q += 512) {
        int j = q % NCP;
        g_CIJ[q] = expf(sm[q] - mx[j]) / sum[j];
    }
}

// ---------------- s = sum_r c[r,j]*u_hat ; v = elementwise squash ----------------
__global__ void route_sv_kernel() {
    int b = blockIdx.x;   // 256
    int t = threadIdx.x;  // 160, t = j*16+o
    __shared__ float cs[RTS * NCP];
    for (int q = t; q < RTS * NCP; q += 160) cs[q] = g_CIJ[q];
    __syncthreads();
    int j = t >> 4;
    const float* uh = &g_UH[(size_t)b * RTS * 160 + t];
    float acc = 0.f;
    for (int r = 0; r < RTS; r++) acc = fmaf(cs[r * NCP + j], uh[(size_t)r * 160], acc);
    float sq = acc * acc;
    float v = sq * acc / ((1.f + sq) * sqrtf(sq));
    g_V[b * 160 + t] = v;
}

// ---------------- agreement: b_ij += mean_b sum_o u_hat*v ----------------
__global__ void route_agree_kernel() {
    int r = blockIdx.x;   // 512
    int b = threadIdx.x;  // 256
    __shared__ float red[256][NCP];
    const float4* up = reinterpret_cast<const float4*>(&g_UH[(size_t)(b * RTS + r) * 160]);
    const float4* vp = reinterpret_cast<const float4*>(&g_V[b * 160]);
    float dj[NCP];
#pragma unroll
    for (int j = 0; j < NCP; j++) dj[j] = 0.f;
#pragma unroll
    for (int q = 0; q < 40; q++) {
        float4 u4 = up[q];
        float4 v4 = vp[q];
        int j = q >> 2;
        dj[j] += u4.x * v4.x + u4.y * v4.y + u4.z * v4.z + u4.w * v4.w;
    }
#pragma unroll
    for (int j = 0; j < NCP; j++) red[b][j] = dj[j];
    __syncthreads();
    if (b < NCP) {
        float s = 0.f;
        for (int q = 0; q < 256; q++) s += red[q][b];
        g_BIJ[r * NCP + b] += s * (1.f / 256.f);
    }
}

// ---------------- classes: norm, legacy softmax over batch axis, argmax ----------------
__global__ void classes_argmax_kernel() {
    int b = threadIdx.x; // 256
    __shared__ float cl[256 * NCP];
    __shared__ float lz[NCP];
    for (int j = 0; j < NCP; j++) {
        float s = 0.f;
        for (int o = 0; o < DOUTC; o++) {
            float v = g_V[b * 160 + j * 16 + o];
            s += v * v;
        }
        cl[b * NCP + j] = sqrtf(s);
    }
    __syncthreads();
    if (b < NCP) {
        float m = -1e30f;
        for (int q = 0; q < 256; q++) m = fmaxf(m, cl[q * NCP + b]);
        float s = 0.f;
        for (int q = 0; q < 256; q++) s += expf(cl[q * NCP + b] - m);
        lz[b] = m + logf(s);
    }
    __syncthreads();
    int best = 0;
    float bv = cl[b * NCP + 0] - lz[0];
    for (int j = 1; j < NCP; j++) {
        float v = cl[b * NCP + j] - lz[j];
        if (v > bv) { bv = v; best = j; }
    }
    g_IDX[b] = best;
}

// ---------------- decoder layer 1 (sparse: only 16 nonzero inputs) ----------------
__global__ void dec1_kernel(const float* __restrict__ w1, const float* __restrict__ b1) {
    int b = blockIdx.x;    // 256
    int k = threadIdx.x;   // 512
    __shared__ float vs[16];
    __shared__ int idx;
    if (k == 0) idx = g_IDX[b];
    __syncthreads();
    if (k < 16) vs[k] = g_V[b * 160 + idx * 16 + k];
    __syncthreads();
    float acc = b1[k];
    const float* wp = &w1[(size_t)k * 160 + idx * 16];
#pragma unroll
    for (int o = 0; o < 16; o++) acc = fmaf(vs[o], wp[o], acc);
    g_H1[b * DEC1 + k] = fmaxf(acc, 0.f);
}

// ---------------- launch ----------------
extern "C" void kernel_launch(void* const* d_in, const int* in_sizes, int n_in,
                              void* d_out, int out_size) {
    const float* data    = (const float*)d_in[0];
    const float* conv1_w = (const float*)d_in[1];
    const float* conv1_b = (const float*)d_in[2];
    const float* prim_w  = (const float*)d_in[3];
    const float* prim_b  = (const float*)d_in[4];
    const float* W_digit = (const float*)d_in[5];
    const float* dec_w1  = (const float*)d_in[6];
    const float* dec_b1  = (const float*)d_in[7];
    const float* dec_w2  = (const float*)d_in[8];
    const float* dec_b2  = (const float*)d_in[9];
    const float* dec_w3  = (const float*)d_in[10];
    const float* dec_b3  = (const float*)d_in[11];
    float* out = (float*)d_out;

    float *pA1, *pW1p, *pC1, *pW2p, *pU, *pH1, *pH2;
    cudaGetSymbolAddress((void**)&pA1,  g_A1);
    cudaGetSymbolAddress((void**)&pW1p, g_W1p);
    cudaGetSymbolAddress((void**)&pC1,  g_C1);
    cudaGetSymbolAddress((void**)&pW2p, g_W2p);
    cudaGetSymbolAddress((void**)&pU,   g_U);
    cudaGetSymbolAddress((void**)&pH1,  g_H1);
    cudaGetSymbolAddress((void**)&pH2,  g_H2);

    // 1) conv1 as GEMM (K padded to 96)
    im2col1_kernel<<<(M1 * K1P + 255) / 256, 256>>>(data);
    permute_w1_kernel<<<(256 * K1P + 255) / 256, 256>>>(conv1_w);
    gemm_nt2<1, 0><<<dim3(M1 / 128, 256 / 64), 256>>>(pA1, pW1p, conv1_b, pC1, M1, 256, K1P);

    // 2) primary caps conv as implicit GEMM (A tiles gathered from g_C1)
    permute_w2_kernel<<<(256 * K2 + 255) / 256, 256>>>(prim_w);
    gemm_nt2<0, 1><<<dim3(M2 / 128, 256 / 64), 256>>>(pC1, pW2p, prim_b, pU, M2, 256, K2);

    // 3) squash + u_hat
    squash_kernel<<<(BSZ * RTS + 255) / 256, 256>>>();
    uhat_kernel<<<RTS, 160>>>(W_digit);

    // 4) dynamic routing (3 iterations, b_ij shared over batch)
    zero_bij_kernel<<<(RTS * NCP + 255) / 256, 256>>>();
    for (int it = 0; it < 3; it++) {
        softmax_routes_kernel<<<1, 512>>>();
        route_sv_kernel<<<BSZ, 160>>>();
        if (it < 2) route_agree_kernel<<<RTS, 256>>>();
    }

    // 5) classes / mask / decoder
    classes_argmax_kernel<<<1, 256>>>();
    dec1_kernel<<<BSZ, DEC1>>>(dec_w1, dec_b1);
    gemm_nt2<1, 0><<<dim3(BSZ / 128, DEC2 / 64), 256>>>(pH1, dec_w2, dec_b2, pH2, BSZ, DEC2, DEC1);
    gemm_nt2<2, 0><<<dim3(BSZ / 128, RECS / 64), 256>>>(pH2, dec_w3, dec_b3, out, BSZ, RECS, DEC2);
}

// round 4
// speedup vs baseline: 2.7595x; 2.6036x over previous
#include <cuda_runtime.h>
#include <cuda_bf16.h>
#include <math.h>
#include <stdint.h>

// ---------------- problem constants ----------------
#define BSZ   256
#define H1S   12
#define P1    144
#define RTS   512
#define NCP   10
#define K1P   128         // conv1 K padded 81 -> 128
#define K2    20736       // 256*81
#define M1    (BSZ*P1)    // 36864
#define M2    4096
#define RECS  102400
#define DEC1  512
#define DEC2  1024

// ---------------- scratch (static device globals; no allocation) ----------------
__device__ __nv_bfloat16 g_A1h[M1 * K1P], g_A1l[M1 * K1P];
__device__ __nv_bfloat16 g_W1h[256 * K1P], g_W1l[256 * K1P];
__device__ __nv_bfloat16 g_C1h[M1 * 256], g_C1l[M1 * 256];
__device__ __nv_bfloat16 g_W2h[256 * K2], g_W2l[256 * K2];
__device__ float         g_U [M2 * 256];
__device__ __nv_bfloat16 g_W3h[(size_t)RECS * 1024], g_W3l[(size_t)RECS * 1024];
__device__ __nv_bfloat16 g_DW2h[DEC2 * DEC1], g_DW2l[DEC2 * DEC1];
__device__ __nv_bfloat16 g_H1h[BSZ * DEC1], g_H1l[BSZ * DEC1];
__device__ __nv_bfloat16 g_H2h[BSZ * DEC2], g_H2l[BSZ * DEC2];
__device__ float g_X [BSZ * RTS * 8];
__device__ float g_UH[(size_t)BSZ * RTS * 160];
__device__ float g_BIJ[RTS * NCP];
__device__ float g_CIJ[RTS * NCP];
__device__ float g_V [BSZ * 160];
__device__ int   g_IDX[BSZ];

// ---------------- helpers ----------------
__device__ __forceinline__ uint32_t smem_u32(const void* p) {
    uint32_t a;
    asm("{ .reg .u64 t; cvta.to.shared.u64 t, %1; cvt.u32.u64 %0, t; }" : "=r"(a) : "l"(p));
    return a;
}
__device__ __forceinline__ void split1(float v, __nv_bfloat16& h, __nv_bfloat16& l) {
    h = __float2bfloat16(v);
    l = __float2bfloat16(v - __bfloat162float(h));
}
__device__ __forceinline__ void ldsm_x4(uint32_t addr, uint32_t* r) {
    asm volatile("ldmatrix.sync.aligned.m8n8.x4.shared.b16 {%0,%1,%2,%3}, [%4];"
        : "=r"(r[0]), "=r"(r[1]), "=r"(r[2]), "=r"(r[3]) : "r"(addr));
}
__device__ __forceinline__ void mma_bf16(float* c, const uint32_t* a, const uint32_t* b) {
    asm volatile(
        "mma.sync.aligned.m16n8k16.row.col.f32.bf16.bf16.f32 "
        "{%0,%1,%2,%3}, {%4,%5,%6,%7}, {%8,%9}, {%0,%1,%2,%3};"
        : "+f"(c[0]), "+f"(c[1]), "+f"(c[2]), "+f"(c[3])
        : "r"(a[0]), "r"(a[1]), "r"(a[2]), "r"(a[3]), "r"(b[0]), "r"(b[1]));
}

// ---------------- HMMA bf16-split NT GEMM ----------------
// C[M,N] = act(A*W^T + bias); A = Ah+Al, W = Wh+Wl (3-term split).
// BM=128, BN=64, BK=32 bf16; 256 threads (8 warps, 4x2); double-buffered smem.
// MODE 0: A[m][K] row-major. MODE 1: implicit im2col from C1 pair [row][256].
// OUT 0: fp32 C.  OUT 1: bf16 hi/lo pair outputs.
template<int MODE, int ACT, int OUT>
__global__ __launch_bounds__(256)
void hmma_gemm(const __nv_bfloat16* __restrict__ Ah, const __nv_bfloat16* __restrict__ Al,
               const __nv_bfloat16* __restrict__ Wh, const __nv_bfloat16* __restrict__ Wl,
               const float* __restrict__ bias,
               float* __restrict__ Cf,
               __nv_bfloat16* __restrict__ Coh, __nv_bfloat16* __restrict__ Col,
               int N, int K)
{
    extern __shared__ char sm[];
    constexpr int AP   = 80;                 // smem row pitch (bytes) for 32 bf16
    constexpr int ABYT = 128 * AP;           // 10240
    constexpr int BBYT = 64 * AP;            // 5120
    constexpr int STG  = 2 * ABYT + 2 * BBYT;// 30720 per stage

    const int t = threadIdx.x;
    const int m0 = blockIdx.x * 128;
    const int n0 = blockIdx.y * 64;
    const uint32_t sbase = smem_u32(sm);

    // per-thread global-load coordinates
    int arow[2], aseg[2], mbase[2];
#pragma unroll
    for (int i = 0; i < 2; i++) {
        int idx = t + i * 256;
        arow[i] = idx >> 2; aseg[i] = idx & 3;
        if (MODE == 1) {
            int m = m0 + arow[i]; int b = m >> 4, p = m & 15;
            mbase[i] = b * 144 + (p >> 2) * 12 + (p & 3);
        }
    }
    const int browg = t >> 2, bseg = t & 3;

    // warp/lane fragment coordinates
    const int w = t >> 5, lane = t & 31;
    const int wm = w & 3, wn = w >> 2;
    const int lrow = (lane & 7) + ((lane >> 3) & 1) * 8;
    const int lk   = ((lane >> 4) & 1) * 8;

    float acc[2][4][4];
#pragma unroll
    for (int mt = 0; mt < 2; mt++)
#pragma unroll
        for (int nt = 0; nt < 4; nt++)
#pragma unroll
            for (int q = 0; q < 4; q++) acc[mt][nt][q] = 0.f;

    uint4 rAh[2], rAl[2], rBh, rBl;

    auto ldg_stage = [&](int k0) {
#pragma unroll
        for (int i = 0; i < 2; i++) {
            size_t off;
            if (MODE == 0) {
                off = (size_t)(m0 + arow[i]) * K + k0 + aseg[i] * 8;
            } else {
                int rr = k0 >> 8;
                int rowg = mbase[i] + (rr / 9) * 12 + (rr % 9);
                off = (size_t)rowg * 256 + (k0 & 255) + aseg[i] * 8;
            }
            rAh[i] = *(const uint4*)(Ah + off);
            rAl[i] = *(const uint4*)(Al + off);
        }
        size_t boff = (size_t)(n0 + browg) * K + k0 + bseg * 8;
        rBh = *(const uint4*)(Wh + boff);
        rBl = *(const uint4*)(Wl + boff);
    };
    auto sts_stage = [&](int buf) {
        char* p = sm + buf * STG;
#pragma unroll
        for (int i = 0; i < 2; i++) {
            *(uint4*)(p + arow[i] * AP + aseg[i] * 16) = rAh[i];
            *(uint4*)(p + ABYT + arow[i] * AP + aseg[i] * 16) = rAl[i];
        }
        *(uint4*)(p + 2 * ABYT + browg * AP + bseg * 16) = rBh;
        *(uint4*)(p + 2 * ABYT + BBYT + browg * AP + bseg * 16) = rBl;
    };
    auto compute = [&](int buf) {
        uint32_t base = sbase + buf * STG;
#pragma unroll
        for (int kk = 0; kk < 32; kk += 16) {
            uint32_t a_h[2][4], a_l[2][4], b_h[2][4], b_l[2][4];
#pragma unroll
            for (int mt = 0; mt < 2; mt++) {
                uint32_t ad = base + (wm * 32 + mt * 16 + lrow) * AP + (kk + lk) * 2;
                ldsm_x4(ad, a_h[mt]);
                ldsm_x4(ad + ABYT, a_l[mt]);
            }
#pragma unroll
            for (int np = 0; np < 2; np++) {
                uint32_t bd = base + 2 * ABYT + (wn * 32 + np * 16 + lrow) * AP + (kk + lk) * 2;
                ldsm_x4(bd, b_h[np]);
                ldsm_x4(bd + BBYT, b_l[np]);
            }
#pragma unroll
            for (int mt = 0; mt < 2; mt++)
#pragma unroll
                for (int nt = 0; nt < 4; nt++) {
                    const uint32_t* bh = &b_h[nt >> 1][(nt & 1) * 2];
                    const uint32_t* bl = &b_l[nt >> 1][(nt & 1) * 2];
                    mma_bf16(acc[mt][nt], a_h[mt], bh);
                    mma_bf16(acc[mt][nt], a_h[mt], bl);
                    mma_bf16(acc[mt][nt], a_l[mt], bh);
                }
        }
    };

    const int S = K / 32;
    ldg_stage(0);
    sts_stage(0);
    __syncthreads();
    for (int s = 0; s < S; s++) {
        if (s + 1 < S) ldg_stage((s + 1) * 32);
        compute(s & 1);
        if (s + 1 < S) sts_stage((s + 1) & 1);
        __syncthreads();
    }

    // ---- epilogue ----
#pragma unroll
    for (int mt = 0; mt < 2; mt++) {
#pragma unroll
        for (int nt = 0; nt < 4; nt++) {
            int row0 = m0 + wm * 32 + mt * 16 + (lane >> 2);
            int col  = n0 + wn * 32 + nt * 8 + (lane & 3) * 2;
            float b0 = bias[col], b1 = bias[col + 1];
#pragma unroll
            for (int half = 0; half < 2; half++) {
                int row = row0 + half * 8;
                float v0 = acc[mt][nt][half * 2 + 0] + b0;
                float v1 = acc[mt][nt][half * 2 + 1] + b1;
                if (ACT == 1) { v0 = fmaxf(v0, 0.f); v1 = fmaxf(v1, 0.f); }
                else if (ACT == 2) {
                    v0 = 1.f / (1.f + expf(-v0));
                    v1 = 1.f / (1.f + expf(-v1));
                }
                if (OUT == 0) {
                    *reinterpret_cast<float2*>(&Cf[(size_t)row * N + col]) = make_float2(v0, v1);
                } else {
                    __nv_bfloat16 h0, l0, h1, l1;
                    split1(v0, h0, l0); split1(v1, h1, l1);
                    __nv_bfloat162 hh = __halves2bfloat162(h0, h1);
                    __nv_bfloat162 ll = __halves2bfloat162(l0, l1);
                    *reinterpret_cast<__nv_bfloat162*>(&Coh[(size_t)row * N + col]) = hh;
                    *reinterpret_cast<__nv_bfloat162*>(&Col[(size_t)row * N + col]) = ll;
                }
            }
        }
    }
}

// ---------------- prep kernels ----------------
__global__ void im2col1_kernel(const float* __restrict__ data) {
    int idx = blockIdx.x * blockDim.x + threadIdx.x;
    if (idx >= M1 * K1P) return;
    int m = idx / K1P, kk = idx % K1P;
    float v = 0.f;
    if (kk < 81) {
        int b = m / P1, pos = m % P1;
        int y = pos / H1S, x = pos % H1S;
        int ky = kk / 9, kx = kk % 9;
        v = data[(size_t)b * 400 + (y + ky) * 20 + (x + kx)];
    }
    split1(v, g_A1h[idx], g_A1l[idx]);
}
__global__ void permute_w1_kernel(const float* __restrict__ conv1_w) {
    int idx = blockIdx.x * blockDim.x + threadIdx.x;
    if (idx >= 256 * K1P) return;
    int o = idx / K1P, kk = idx % K1P;
    float v = (kk < 81) ? conv1_w[o * 81 + kk] : 0.f;
    split1(v, g_W1h[idx], g_W1l[idx]);
}
__global__ void permute_w2_kernel(const float* __restrict__ prim_w) {
    int idx = blockIdx.x * blockDim.x + threadIdx.x;
    if (idx >= 256 * K2) return;
    int o = idx / K2, rem = idx % K2;
    int rr = rem >> 8, c = rem & 255;
    float v = prim_w[(size_t)o * K2 + c * 81 + rr];
    split1(v, g_W2h[idx], g_W2l[idx]);
}
__global__ void split4_kernel(const float4* __restrict__ src,
                              uint2* __restrict__ hi, uint2* __restrict__ lo, int n4) {
    int i = blockIdx.x * blockDim.x + threadIdx.x;
    if (i >= n4) return;
    float4 v = src[i];
    __nv_bfloat16 hx, hy, hz, hw, lx, ly, lz, lw;
    split1(v.x, hx, lx); split1(v.y, hy, ly); split1(v.z, hz, lz); split1(v.w, hw, lw);
    __nv_bfloat162 h01 = __halves2bfloat162(hx, hy), h23 = __halves2bfloat162(hz, hw);
    __nv_bfloat162 l01 = __halves2bfloat162(lx, ly), l23 = __halves2bfloat162(lz, lw);
    hi[i] = make_uint2(*reinterpret_cast<uint32_t*>(&h01), *reinterpret_cast<uint32_t*>(&h23));
    lo[i] = make_uint2(*reinterpret_cast<uint32_t*>(&l01), *reinterpret_cast<uint32_t*>(&l23));
}

// ---------------- capsule / routing kernels ----------------
__global__ void squash_kernel() {
    int t = blockIdx.x * blockDim.x + threadIdx.x;
    if (t >= BSZ * RTS) return;
    int b = t / RTS, r = t % RTS;
    int o = r >> 1, hi = r & 1;
    const float* up = &g_U[(size_t)(b * 16 + hi * 8) * 256 + o];
    float u[8], sn = 0.f;
#pragma unroll
    for (int i = 0; i < 8; i++) { u[i] = up[(size_t)i * 256]; sn += u[i] * u[i]; }
    float sc = sn / ((1.f + sn) * sqrtf(sn));
#pragma unroll
    for (int i = 0; i < 8; i++) g_X[(size_t)t * 8 + i] = u[i] * sc;
}
__global__ void uhat_kernel(const float* __restrict__ Wd) {
    int r = blockIdx.x;        // 512
    int b0 = blockIdx.y * 32;  // 8 batch chunks
    int t = threadIdx.x;       // 160: t = c*16+o
    __shared__ float Wr[1280];
    __shared__ float Xr[256];
    for (int q = t; q < 1280; q += 160) Wr[q] = Wd[(size_t)r * 1280 + q];
    for (int q = t; q < 256; q += 160) {
        int b = q >> 3, i = q & 7;
        Xr[q] = g_X[(size_t)((b0 + b) * RTS + r) * 8 + i];
    }
    __syncthreads();
    for (int b = 0; b < 32; b++) {
        float acc = 0.f;
#pragma unroll
        for (int i = 0; i < 8; i++) acc = fmaf(Wr[t * 8 + i], Xr[b * 8 + i], acc);
        g_UH[(size_t)((b0 + b) * RTS + r) * 160 + t] = acc;
    }
}
__global__ void zero_bij_kernel() {
    int t = blockIdx.x * blockDim.x + threadIdx.x;
    if (t < RTS * NCP) g_BIJ[t] = 0.f;
}
__global__ void softmax_routes_kernel() {
    __shared__ float sm[RTS * NCP];
    __shared__ float mx[NCP], sum[NCP];
    int t = threadIdx.x; // 512
    for (int q = t; q < RTS * NCP; q += 512) sm[q] = g_BIJ[q];
    __syncthreads();
    if (t < NCP) {
        float m = -1e30f;
        for (int r = 0; r < RTS; r++) m = fmaxf(m, sm[r * NCP + t]);
        float s = 0.f;
        for (int r = 0; r < RTS; r++) s += expf(sm[r * NCP + t] - m);
        mx[t] = m; sum[t] = s;
    }
    __syncthreads();
    for (int q = t; q < RTS * NCP; q += 512) {
        int j = q % NCP;
        g_CIJ[q] = expf(sm[q] - mx[j]) / sum[j];
    }
}
__global__ void route_sv_kernel() {
    int b = blockIdx.x;   // 256
    int t = threadIdx.x;  // 160, t = j*16+o
    __shared__ float cs[RTS * NCP];
    for (int q = t; q < RTS * NCP; q += 160) cs[q] = g_CIJ[q];
    __syncthreads();
    int j = t >> 4;
    const float* uh = &g_UH[(size_t)b * RTS * 160 + t];
    float acc = 0.f;
    for (int r = 0; r < RTS; r++) acc = fmaf(cs[r * NCP + j], uh[(size_t)r * 160], acc);
    float sq = acc * acc;
    float v = sq * acc / ((1.f + sq) * sqrtf(sq));
    g_V[b * 160 + t] = v;
}
__global__ void route_agree_kernel() {
    int r = blockIdx.x;   // 512
    int b = threadIdx.x;  // 256
    __shared__ float red[256][NCP];
    const float4* up = reinterpret_cast<const float4*>(&g_UH[(size_t)(b * RTS + r) * 160]);
    const float4* vp = reinterpret_cast<const float4*>(&g_V[b * 160]);
    float dj[NCP];
#pragma unroll
    for (int j = 0; j < NCP; j++) dj[j] = 0.f;
#pragma unroll
    for (int q = 0; q < 40; q++) {
        float4 u4 = up[q], v4 = vp[q];
        int j = q >> 2;
        dj[j] += u4.x * v4.x + u4.y * v4.y + u4.z * v4.z + u4.w * v4.w;
    }
#pragma unroll
    for (int j = 0; j < NCP; j++) red[b][j] = dj[j];
    __syncthreads();
    if (b < NCP) {
        float s = 0.f;
        for (int q = 0; q < 256; q++) s += red[q][b];
        g_BIJ[r * NCP + b] += s * (1.f / 256.f);
    }
}
__global__ void classes_argmax_kernel() {
    int b = threadIdx.x; // 256
    __shared__ float cl[256 * NCP];
    __shared__ float lz[NCP];
    for (int j = 0; j < NCP; j++) {
        float s = 0.f;
        for (int o = 0; o < 16; o++) {
            float v = g_V[b * 160 + j * 16 + o];
            s += v * v;
        }
        cl[b * NCP + j] = sqrtf(s);
    }
    __syncthreads();
    if (b < NCP) {
        float m = -1e30f;
        for (int q = 0; q < 256; q++) m = fmaxf(m, cl[q * NCP + b]);
        float s = 0.f;
        for (int q = 0; q < 256; q++) s += expf(cl[q * NCP + b] - m);
        lz[b] = m + logf(s);
    }
    __syncthreads();
    int best = 0;
    float bv = cl[b * NCP + 0] - lz[0];
    for (int j = 1; j < NCP; j++) {
        float v = cl[b * NCP + j] - lz[j];
        if (v > bv) { bv = v; best = j; }
    }
    g_IDX[b] = best;
}
__global__ void dec1_kernel(const float* __restrict__ w1, const float* __restrict__ b1) {
    int b = blockIdx.x;    // 256
    int k = threadIdx.x;   // 512
    __shared__ float vs[16];
    __shared__ int idx;
    if (k == 0) idx = g_IDX[b];
    __syncthreads();
    if (k < 16) vs[k] = g_V[b * 160 + idx * 16 + k];
    __syncthreads();
    float acc = b1[k];
    const float* wp = &w1[(size_t)k * 160 + idx * 16];
#pragma unroll
    for (int o = 0; o < 16; o++) acc = fmaf(vs[o], wp[o], acc);
    float v = fmaxf(acc, 0.f);
    split1(v, g_H1h[b * DEC1 + k], g_H1l[b * DEC1 + k]);
}

// ---------------- launch ----------------
extern "C" void kernel_launch(void* const* d_in, const int* in_sizes, int n_in,
                              void* d_out, int out_size) {
    const float* data    = (const float*)d_in[0];
    const float* conv1_w = (const float*)d_in[1];
    const float* conv1_b = (const float*)d_in[2];
    const float* prim_w  = (const float*)d_in[3];
    const float* prim_b  = (const float*)d_in[4];
    const float* W_digit = (const float*)d_in[5];
    const float* dec_w1  = (const float*)d_in[6];
    const float* dec_b1  = (const float*)d_in[7];
    const float* dec_w2  = (const float*)d_in[8];
    const float* dec_b2  = (const float*)d_in[9];
    const float* dec_w3  = (const float*)d_in[10];
    const float* dec_b3  = (const float*)d_in[11];
    float* out = (float*)d_out;

    __nv_bfloat16 *pA1h, *pA1l, *pW1h, *pW1l, *pC1h, *pC1l, *pW2h, *pW2l;
    __nv_bfloat16 *pW3h, *pW3l, *pDW2h, *pDW2l, *pH1h, *pH1l, *pH2h, *pH2l;
    float *pU;
    cudaGetSymbolAddress((void**)&pA1h, g_A1h);  cudaGetSymbolAddress((void**)&pA1l, g_A1l);
    cudaGetSymbolAddress((void**)&pW1h, g_W1h);  cudaGetSymbolAddress((void**)&pW1l, g_W1l);
    cudaGetSymbolAddress((void**)&pC1h, g_C1h);  cudaGetSymbolAddress((void**)&pC1l, g_C1l);
    cudaGetSymbolAddress((void**)&pW2h, g_W2h);  cudaGetSymbolAddress((void**)&pW2l, g_W2l);
    cudaGetSymbolAddress((void**)&pW3h, g_W3h);  cudaGetSymbolAddress((void**)&pW3l, g_W3l);
    cudaGetSymbolAddress((void**)&pDW2h, g_DW2h); cudaGetSymbolAddress((void**)&pDW2l, g_DW2l);
    cudaGetSymbolAddress((void**)&pH1h, g_H1h);  cudaGetSymbolAddress((void**)&pH1l, g_H1l);
    cudaGetSymbolAddress((void**)&pH2h, g_H2h);  cudaGetSymbolAddress((void**)&pH2l, g_H2l);
    cudaGetSymbolAddress((void**)&pU, g_U);

    constexpr int SMB = 2 * (2 * 128 * 80 + 2 * 64 * 80);  // 61440
    cudaFuncSetAttribute(hmma_gemm<0, 1, 1>, cudaFuncAttributeMaxDynamicSharedMemorySize, SMB);
    cudaFuncSetAttribute(hmma_gemm<1, 0, 0>, cudaFuncAttributeMaxDynamicSharedMemorySize, SMB);
    cudaFuncSetAttribute(hmma_gemm<0, 2, 0>, cudaFuncAttributeMaxDynamicSharedMemorySize, SMB);

    // weight preps
    permute_w1_kernel<<<(256 * K1P + 255) / 256, 256>>>(conv1_w);
    permute_w2_kernel<<<(256 * K2 + 255) / 256, 256>>>(prim_w);
    split4_kernel<<<(DEC2 * DEC1 / 4 + 255) / 256, 256>>>(
        (const float4*)dec_w2, (uint2*)pDW2h, (uint2*)pDW2l, DEC2 * DEC1 / 4);
    split4_kernel<<<(int)(((size_t)RECS * 1024 / 4 + 255) / 256), 256>>>(
        (const float4*)dec_w3, (uint2*)pW3h, (uint2*)pW3l, (int)((size_t)RECS * 1024 / 4));

    // 1) conv1 (HMMA, relu, bf16-pair out)
    im2col1_kernel<<<(M1 * K1P + 255) / 256, 256>>>(data);
    hmma_gemm<0, 1, 1><<<dim3(M1 / 128, 256 / 64), 256, SMB>>>(
        pA1h, pA1l, pW1h, pW1l, conv1_b, nullptr, pC1h, pC1l, 256, K1P);

    // 2) primary caps (implicit im2col HMMA, fp32 out)
    hmma_gemm<1, 0, 0><<<dim3(M2 / 128, 256 / 64), 256, SMB>>>(
        pC1h, pC1l, pW2h, pW2l, prim_b, pU, nullptr, nullptr, 256, K2);

    // 3) squash + u_hat
    squash_kernel<<<(BSZ * RTS + 255) / 256, 256>>>();
    uhat_kernel<<<dim3(RTS, 8), 160>>>(W_digit);

    // 4) dynamic routing
    zero_bij_kernel<<<(RTS * NCP + 255) / 256, 256>>>();
    for (int it = 0; it < 3; it++) {
        softmax_routes_kernel<<<1, 512>>>();
        route_sv_kernel<<<BSZ, 160>>>();
        if (it < 2) route_agree_kernel<<<RTS, 256>>>();
    }

    // 5) classes / mask / decoder
    classes_argmax_kernel<<<1, 256>>>();
    dec1_kernel<<<BSZ, DEC1>>>(dec_w1, dec_b1);
    hmma_gemm<0, 1, 1><<<dim3(BSZ / 128, DEC2 / 64), 256, SMB>>>(
        pH1h, pH1l, pDW2h, pDW2l, dec_b2, nullptr, pH2h, pH2l, DEC2, DEC1);
    hmma_gemm<0, 2, 0><<<dim3(BSZ / 128, RECS / 64), 256, SMB>>>(
        pH2h, pH2l, pW3h, pW3l, dec_b3, out, nullptr, nullptr, RECS, DEC2);
}

// round 5
// speedup vs baseline: 3.2301x; 1.1705x over previous
#include <cuda_runtime.h>
#include <cuda_bf16.h>
#include <math.h>
#include <stdint.h>

// ---------------- problem constants ----------------
#define BSZ   256
#define H1S   12
#define P1    144
#define RTS   512
#define NCP   10
#define K1P   128
#define K2    20736
#define M1    (BSZ*P1)    // 36864
#define M2    4096
#define RECS  102400
#define DEC1  512
#define DEC2  1024

// ---------------- scratch ----------------
__device__ __nv_bfloat16 g_A1h[M1 * K1P], g_A1l[M1 * K1P];
__device__ __nv_bfloat16 g_W1h[256 * K1P], g_W1l[256 * K1P];
__device__ __nv_bfloat16 g_C1h[M1 * 256], g_C1l[M1 * 256];
__device__ __nv_bfloat16 g_W2h[256 * K2];
__device__ float         g_U [M2 * 256];
__device__ __nv_bfloat16 g_H1h[BSZ * DEC1], g_H1l[BSZ * DEC1];
__device__ __nv_bfloat16 g_H2h[BSZ * DEC2], g_H2l[BSZ * DEC2];
__device__ float g_X [BSZ * RTS * 8];
__device__ float g_UH[(size_t)BSZ * RTS * 160];
__device__ float g_BIJ[RTS * NCP];
__device__ float g_CIJ[RTS * NCP];
__device__ float g_V [BSZ * 160];
__device__ int   g_IDX[BSZ];

// ---------------- helpers ----------------
__device__ __forceinline__ uint32_t smem_u32(const void* p) {
    uint32_t a;
    asm("{ .reg .u64 t; cvta.to.shared.u64 t, %1; cvt.u32.u64 %0, t; }" : "=r"(a) : "l"(p));
    return a;
}
__device__ __forceinline__ void split1(float v, __nv_bfloat16& h, __nv_bfloat16& l) {
    h = __float2bfloat16(v);
    l = __float2bfloat16(v - __bfloat162float(h));
}
__device__ __forceinline__ void ldsm_x4(uint32_t addr, uint32_t* r) {
    asm volatile("ldmatrix.sync.aligned.m8n8.x4.shared.b16 {%0,%1,%2,%3}, [%4];"
        : "=r"(r[0]), "=r"(r[1]), "=r"(r[2]), "=r"(r[3]) : "r"(addr));
}
__device__ __forceinline__ void mma_bf16(float* c, const uint32_t* a, const uint32_t* b) {
    asm volatile(
        "mma.sync.aligned.m16n8k16.row.col.f32.bf16.bf16.f32 "
        "{%0,%1,%2,%3}, {%4,%5,%6,%7}, {%8,%9}, {%0,%1,%2,%3};"
        : "+f"(c[0]), "+f"(c[1]), "+f"(c[2]), "+f"(c[3])
        : "r"(a[0]), "r"(a[1]), "r"(a[2]), "r"(a[3]), "r"(b[0]), "r"(b[1]));
}
__device__ __forceinline__ uint4 pack8bf16(float4 f0, float4 f1) {
    __nv_bfloat162 p0 = __halves2bfloat162(__float2bfloat16(f0.x), __float2bfloat16(f0.y));
    __nv_bfloat162 p1 = __halves2bfloat162(__float2bfloat16(f0.z), __float2bfloat16(f0.w));
    __nv_bfloat162 p2 = __halves2bfloat162(__float2bfloat16(f1.x), __float2bfloat16(f1.y));
    __nv_bfloat162 p3 = __halves2bfloat162(__float2bfloat16(f1.z), __float2bfloat16(f1.w));
    uint4 r;
    r.x = *reinterpret_cast<uint32_t*>(&p0);
    r.y = *reinterpret_cast<uint32_t*>(&p1);
    r.z = *reinterpret_cast<uint32_t*>(&p2);
    r.w = *reinterpret_cast<uint32_t*>(&p3);
    return r;
}

// ---------------- HMMA split NT GEMM ----------------
// C[M,N] = act(A*W^T + bias).
// TERMS 3: A=(ah+al), W=(wh+wl): ah*wh + ah*wl + al*wh   (error ~2^-16)
// TERMS 2: A=(ah+al), W=wh only: ah*wh + al*wh           (error ~2^-9, stochastic)
// WFP32 1: W supplied as fp32 (Wf), converted to bf16 hi in the loader.
// MODE 1: implicit im2col of A from C1 pair [row][256], k=(rr*256+c).
// OUT 0: fp32 C.  OUT 1: bf16 hi/lo pair outputs.
template<int MODE, int ACT, int OUT, int TERMS, int WFP32>
__global__ __launch_bounds__(256)
void hmma_gemm(const __nv_bfloat16* __restrict__ Ah, const __nv_bfloat16* __restrict__ Al,
               const __nv_bfloat16* __restrict__ Wh, const __nv_bfloat16* __restrict__ Wl,
               const float* __restrict__ Wf,
               const float* __restrict__ bias,
               float* __restrict__ Cf,
               __nv_bfloat16* __restrict__ Coh, __nv_bfloat16* __restrict__ Col,
               int N, int K)
{
    extern __shared__ char sm[];
    constexpr int AP   = 80;
    constexpr int ABYT = 128 * AP;
    constexpr int BBYT = 64 * AP;
    constexpr int NB   = (TERMS == 3) ? 2 : 1;   // B operands in smem
    constexpr int STG  = 2 * ABYT + NB * BBYT;

    const int t = threadIdx.x;
    const int m0 = blockIdx.x * 128;
    const int n0 = blockIdx.y * 64;
    const uint32_t sbase = smem_u32(sm);

    int arow[2], aseg[2], mbase[2];
#pragma unroll
    for (int i = 0; i < 2; i++) {
        int idx = t + i * 256;
        arow[i] = idx >> 2; aseg[i] = idx & 3;
        if (MODE == 1) {
            int m = m0 + arow[i]; int b = m >> 4, p = m & 15;
            mbase[i] = b * 144 + (p >> 2) * 12 + (p & 3);
        }
    }
    const int browg = t >> 2, bseg = t & 3;

    const int w = t >> 5, lane = t & 31;
    const int wm = w & 3, wn = w >> 2;
    const int lrow = (lane & 7) + ((lane >> 3) & 1) * 8;
    const int lk   = ((lane >> 4) & 1) * 8;

    float acc[2][4][4];
#pragma unroll
    for (int mt = 0; mt < 2; mt++)
#pragma unroll
        for (int nt = 0; nt < 4; nt++)
#pragma unroll
            for (int q = 0; q < 4; q++) acc[mt][nt][q] = 0.f;

    uint4 rAh[2], rAl[2], rBh, rBl;

    auto ldg_stage = [&](int k0) {
#pragma unroll
        for (int i = 0; i < 2; i++) {
            size_t off;
            if (MODE == 0) {
                off = (size_t)(m0 + arow[i]) * K + k0 + aseg[i] * 8;
            } else {
                int rr = k0 >> 8;
                int rowg = mbase[i] + (rr / 9) * 12 + (rr % 9);
                off = (size_t)rowg * 256 + (k0 & 255) + aseg[i] * 8;
            }
            rAh[i] = *(const uint4*)(Ah + off);
            rAl[i] = *(const uint4*)(Al + off);
        }
        size_t boff = (size_t)(n0 + browg) * K + k0 + bseg * 8;
        if (WFP32) {
            const float* wp = Wf + boff;
            float4 f0 = *(const float4*)wp;
            float4 f1 = *(const float4*)(wp + 4);
            rBh = pack8bf16(f0, f1);
        } else {
            rBh = *(const uint4*)(Wh + boff);
            if (TERMS == 3) rBl = *(const uint4*)(Wl + boff);
        }
    };
    auto sts_stage = [&](int buf) {
        char* p = sm + buf * STG;
#pragma unroll
        for (int i = 0; i < 2; i++) {
            *(uint4*)(p + arow[i] * AP + aseg[i] * 16) = rAh[i];
            *(uint4*)(p + ABYT + arow[i] * AP + aseg[i] * 16) = rAl[i];
        }
        *(uint4*)(p + 2 * ABYT + browg * AP + bseg * 16) = rBh;
        if (TERMS == 3)
            *(uint4*)(p + 2 * ABYT + BBYT + browg * AP + bseg * 16) = rBl;
    };
    auto compute = [&](int buf) {
        uint32_t base = sbase + buf * STG;
#pragma unroll
        for (int kk = 0; kk < 32; kk += 16) {
            uint32_t a_h[2][4], a_l[2][4], b_h[2][4], b_l[2][4];
#pragma unroll
            for (int mt = 0; mt < 2; mt++) {
                uint32_t ad = base + (wm * 32 + mt * 16 + lrow) * AP + (kk + lk) * 2;
                ldsm_x4(ad, a_h[mt]);
                ldsm_x4(ad + ABYT, a_l[mt]);
            }
#pragma unroll
            for (int np = 0; np < 2; np++) {
                uint32_t bd = base + 2 * ABYT + (wn * 32 + np * 16 + lrow) * AP + (kk + lk) * 2;
                ldsm_x4(bd, b_h[np]);
                if (TERMS == 3) ldsm_x4(bd + BBYT, b_l[np]);
            }
#pragma unroll
            for (int mt = 0; mt < 2; mt++)
#pragma unroll
                for (int nt = 0; nt < 4; nt++) {
                    const uint32_t* bh = &b_h[nt >> 1][(nt & 1) * 2];
                    mma_bf16(acc[mt][nt], a_h[mt], bh);
                    if (TERMS == 3) {
                        const uint32_t* bl = &b_l[nt >> 1][(nt & 1) * 2];
                        mma_bf16(acc[mt][nt], a_h[mt], bl);
                    }
                    mma_bf16(acc[mt][nt], a_l[mt], bh);
                }
        }
    };

    const int S = K / 32;
    ldg_stage(0);
    sts_stage(0);
    __syncthreads();
    for (int s = 0; s < S; s++) {
        if (s + 1 < S) ldg_stage((s + 1) * 32);
        compute(s & 1);
        if (s + 1 < S) sts_stage((s + 1) & 1);
        __syncthreads();
    }

    // ---- epilogue ----
#pragma unroll
    for (int mt = 0; mt < 2; mt++) {
#pragma unroll
        for (int nt = 0; nt < 4; nt++) {
            int row0 = m0 + wm * 32 + mt * 16 + (lane >> 2);
            int col  = n0 + wn * 32 + nt * 8 + (lane & 3) * 2;
            float b0 = bias[col], b1 = bias[col + 1];
#pragma unroll
            for (int half = 0; half < 2; half++) {
                int row = row0 + half * 8;
                float v0 = acc[mt][nt][half * 2 + 0] + b0;
                float v1 = acc[mt][nt][half * 2 + 1] + b1;
                if (ACT == 1) { v0 = fmaxf(v0, 0.f); v1 = fmaxf(v1, 0.f); }
                else if (ACT == 2) {
                    v0 = 1.f / (1.f + expf(-v0));
                    v1 = 1.f / (1.f + expf(-v1));
                }
                if (OUT == 0) {
                    *reinterpret_cast<float2*>(&Cf[(size_t)row * N + col]) = make_float2(v0, v1);
                } else {
                    __nv_bfloat16 h0, l0, h1, l1;
                    split1(v0, h0, l0); split1(v1, h1, l1);
                    __nv_bfloat162 hh = __halves2bfloat162(h0, h1);
                    __nv_bfloat162 ll = __halves2bfloat162(l0, l1);
                    *reinterpret_cast<__nv_bfloat162*>(&Coh[(size_t)row * N + col]) = hh;
                    *reinterpret_cast<__nv_bfloat162*>(&Col[(size_t)row * N + col]) = ll;
                }
            }
        }
    }
}

// ---------------- prep kernels ----------------
__global__ void im2col1_kernel(const float* __restrict__ data) {
    int idx = blockIdx.x * blockDim.x + threadIdx.x;
    if (idx >= M1 * K1P) return;
    int m = idx / K1P, kk = idx % K1P;
    float v = 0.f;
    if (kk < 81) {
        int b = m / P1, pos = m % P1;
        int y = pos / H1S, x = pos % H1S;
        int ky = kk / 9, kx = kk % 9;
        v = data[(size_t)b * 400 + (y + ky) * 20 + (x + kx)];
    }
    split1(v, g_A1h[idx], g_A1l[idx]);
}
__global__ void permute_w1_kernel(const float* __restrict__ conv1_w) {
    int idx = blockIdx.x * blockDim.x + threadIdx.x;
    if (idx >= 256 * K1P) return;
    int o = idx / K1P, kk = idx % K1P;
    float v = (kk < 81) ? conv1_w[o * 81 + kk] : 0.f;
    split1(v, g_W1h[idx], g_W1l[idx]);
}
__global__ void permute_w2_kernel(const float* __restrict__ prim_w) {
    int idx = blockIdx.x * blockDim.x + threadIdx.x;
    if (idx >= 256 * K2) return;
    int o = idx / K2, rem = idx % K2;
    int rr = rem >> 8, c = rem & 255;
    g_W2h[idx] = __float2bfloat16(prim_w[(size_t)o * K2 + c * 81 + rr]);
}

// ---------------- capsule / routing kernels ----------------
__global__ void squash_kernel() {
    int t = blockIdx.x * blockDim.x + threadIdx.x;
    if (t >= BSZ * RTS) return;
    int b = t / RTS, r = t % RTS;
    int o = r >> 1, hi = r & 1;
    const float* up = &g_U[(size_t)(b * 16 + hi * 8) * 256 + o];
    float u[8], sn = 0.f;
#pragma unroll
    for (int i = 0; i < 8; i++) { u[i] = up[(size_t)i * 256]; sn += u[i] * u[i]; }
    float sc = sn / ((1.f + sn) * sqrtf(sn));
#pragma unroll
    for (int i = 0; i < 8; i++) g_X[(size_t)t * 8 + i] = u[i] * sc;
}
__global__ void uhat_kernel(const float* __restrict__ Wd) {
    int r = blockIdx.x;
    int b0 = blockIdx.y * 32;
    int t = threadIdx.x;       // 160: t = c*16+o
    __shared__ float Wr[1280];
    __shared__ float Xr[256];
    for (int q = t; q < 1280; q += 160) Wr[q] = Wd[(size_t)r * 1280 + q];
    for (int q = t; q < 256; q += 160) {
        int b = q >> 3, i = q & 7;
        Xr[q] = g_X[(size_t)((b0 + b) * RTS + r) * 8 + i];
    }
    __syncthreads();
    for (int b = 0; b < 32; b++) {
        float acc = 0.f;
#pragma unroll
        for (int i = 0; i < 8; i++) acc = fmaf(Wr[t * 8 + i], Xr[b * 8 + i], acc);
        g_UH[(size_t)((b0 + b) * RTS + r) * 160 + t] = acc;
    }
}
__global__ void zero_bij_kernel() {
    int t = blockIdx.x * blockDim.x + threadIdx.x;
    if (t < RTS * NCP) g_BIJ[t] = 0.f;
}
__global__ void softmax_routes_kernel() {
    __shared__ float sm[RTS * NCP];
    __shared__ float mx[NCP], sum[NCP];
    int t = threadIdx.x; // 512
    for (int q = t; q < RTS * NCP; q += 512) sm[q] = g_BIJ[q];
    __syncthreads();
    if (t < NCP) {
        float m = -1e30f;
        for (int r = 0; r < RTS; r++) m = fmaxf(m, sm[r * NCP + t]);
        float s = 0.f;
        for (int r = 0; r < RTS; r++) s += expf(sm[r * NCP + t] - m);
        mx[t] = m; sum[t] = s;
    }
    __syncthreads();
    for (int q = t; q < RTS * NCP; q += 512) {
        int j = q % NCP;
        g_CIJ[q] = expf(sm[q] - mx[j]) / sum[j];
    }
}
__global__ void route_sv_kernel() {
    int b = blockIdx.x;   // 256
    int t = threadIdx.x;  // 160, t = j*16+o
    __shared__ float cs[RTS * NCP];
    for (int q = t; q < RTS * NCP; q += 160) cs[q] = g_CIJ[q];
    __syncthreads();
    int j = t >> 4;
    const float* uh = &g_UH[(size_t)b * RTS * 160 + t];
    float acc = 0.f;
    for (int r = 0; r < RTS; r++) acc = fmaf(cs[r * NCP + j], uh[(size_t)r * 160], acc);
    float sq = acc * acc;
    float v = sq * acc / ((1.f + sq) * sqrtf(sq));
    g_V[b * 160 + t] = v;
}
__global__ void route_agree_kernel() {
    int r = blockIdx.x;   // 512
    int b = threadIdx.x;  // 256
    __shared__ float red[256][NCP];
    const float4* up = reinterpret_cast<const float4*>(&g_UH[(size_t)(b * RTS + r) * 160]);
    const float4* vp = reinterpret_cast<const float4*>(&g_V[b * 160]);
    float dj[NCP];
#pragma unroll
    for (int j = 0; j < NCP; j++) dj[j] = 0.f;
#pragma unroll
    for (int q = 0; q < 40; q++) {
        float4 u4 = up[q], v4 = vp[q];
        int j = q >> 2;
        dj[j] += u4.x * v4.x + u4.y * v4.y + u4.z * v4.z + u4.w * v4.w;
    }
#pragma unroll
    for (int j = 0; j < NCP; j++) red[b][j] = dj[j];
    __syncthreads();
    if (b < NCP) {
        float s = 0.f;
        for (int q = 0; q < 256; q++) s += red[q][b];
        g_BIJ[r * NCP + b] += s * (1.f / 256.f);
    }
}
__global__ void classes_argmax_kernel() {
    int b = threadIdx.x; // 256
    __shared__ float cl[256 * NCP];
    __shared__ float lz[NCP];
    for (int j = 0; j < NCP; j++) {
        float s = 0.f;
        for (int o = 0; o < 16; o++) {
            float v = g_V[b * 160 + j * 16 + o];
            s += v * v;
        }
        cl[b * NCP + j] = sqrtf(s);
    }
    __syncthreads();
    if (b < NCP) {
        float m = -1e30f;
        for (int q = 0; q < 256; q++) m = fmaxf(m, cl[q * NCP + b]);
        float s = 0.f;
        for (int q = 0; q < 256; q++) s += expf(cl[q * NCP + b] - m);
        lz[b] = m + logf(s);
    }
    __syncthreads();
    int best = 0;
    float bv = cl[b * NCP + 0] - lz[0];
    for (int j = 1; j < NCP; j++) {
        float v = cl[b * NCP + j] - lz[j];
        if (v > bv) { bv = v; best = j; }
    }
    g_IDX[b] = best;
}
__global__ void dec1_kernel(const float* __restrict__ w1, const float* __restrict__ b1) {
    int b = blockIdx.x;    // 256
    int k = threadIdx.x;   // 512
    __shared__ float vs[16];
    __shared__ int idx;
    if (k == 0) idx = g_IDX[b];
    __syncthreads();
    if (k < 16) vs[k] = g_V[b * 160 + idx * 16 + k];
    __syncthreads();
    float acc = b1[k];
    const float* wp = &w1[(size_t)k * 160 + idx * 16];
#pragma unroll
    for (int o = 0; o < 16; o++) acc = fmaf(vs[o], wp[o], acc);
    float v = fmaxf(acc, 0.f);
    split1(v, g_H1h[b * DEC1 + k], g_H1l[b * DEC1 + k]);
}

// ---------------- launch ----------------
extern "C" void kernel_launch(void* const* d_in, const int* in_sizes, int n_in,
                              void* d_out, int out_size) {
    const float* data    = (const float*)d_in[0];
    const float* conv1_w = (const float*)d_in[1];
    const float* conv1_b = (const float*)d_in[2];
    const float* prim_w  = (const float*)d_in[3];
    const float* prim_b  = (const float*)d_in[4];
    const float* W_digit = (const float*)d_in[5];
    const float* dec_w1  = (const float*)d_in[6];
    const float* dec_b1  = (const float*)d_in[7];
    const float* dec_w2  = (const float*)d_in[8];
    const float* dec_b2  = (const float*)d_in[9];
    const float* dec_w3  = (const float*)d_in[10];
    const float* dec_b3  = (const float*)d_in[11];
    float* out = (float*)d_out;

    __nv_bfloat16 *pA1h, *pA1l, *pW1h, *pW1l, *pC1h, *pC1l, *pW2h;
    __nv_bfloat16 *pH1h, *pH1l, *pH2h, *pH2l;
    float *pU;
    cudaGetSymbolAddress((void**)&pA1h, g_A1h);  cudaGetSymbolAddress((void**)&pA1l, g_A1l);
    cudaGetSymbolAddress((void**)&pW1h, g_W1h);  cudaGetSymbolAddress((void**)&pW1l, g_W1l);
    cudaGetSymbolAddress((void**)&pC1h, g_C1h);  cudaGetSymbolAddress((void**)&pC1l, g_C1l);
    cudaGetSymbolAddress((void**)&pW2h, g_W2h);
    cudaGetSymbolAddress((void**)&pH1h, g_H1h);  cudaGetSymbolAddress((void**)&pH1l, g_H1l);
    cudaGetSymbolAddress((void**)&pH2h, g_H2h);  cudaGetSymbolAddress((void**)&pH2l, g_H2l);
    cudaGetSymbolAddress((void**)&pU, g_U);

    constexpr int SMB3 = 2 * (2 * 128 * 80 + 2 * 64 * 80);  // 61440
    constexpr int SMB2 = 2 * (2 * 128 * 80 + 1 * 64 * 80);  // 51200
    cudaFuncSetAttribute((const void*)hmma_gemm<0, 1, 1, 3, 0>, cudaFuncAttributeMaxDynamicSharedMemorySize, SMB3);
    cudaFuncSetAttribute((const void*)hmma_gemm<1, 0, 0, 2, 0>, cudaFuncAttributeMaxDynamicSharedMemorySize, SMB2);
    cudaFuncSetAttribute((const void*)hmma_gemm<0, 1, 1, 2, 1>, cudaFuncAttributeMaxDynamicSharedMemorySize, SMB2);
    cudaFuncSetAttribute((const void*)hmma_gemm<0, 2, 0, 2, 1>, cudaFuncAttributeMaxDynamicSharedMemorySize, SMB2);

    // weight preps (cheap ones only; dec_w2/dec_w3 are converted in-GEMM)
    permute_w1_kernel<<<(256 * K1P + 255) / 256, 256>>>(conv1_w);
    permute_w2_kernel<<<(256 * K2 + 255) / 256, 256>>>(prim_w);

    // 1) conv1: 3-term split HMMA, relu, bf16-pair out
    im2col1_kernel<<<(M1 * K1P + 255) / 256, 256>>>(data);
    hmma_gemm<0, 1, 1, 3, 0><<<dim3(M1 / 128, 256 / 64), 256, SMB3>>>(
        pA1h, pA1l, pW1h, pW1l, nullptr, conv1_b, nullptr, pC1h, pC1l, 256, K1P);

    // 2) primary caps: implicit im2col, 2-term (A split, W bf16), fp32 out
    hmma_gemm<1, 0, 0, 2, 0><<<dim3(M2 / 128, 256 / 64), 256, SMB2>>>(
        pC1h, pC1l, pW2h, nullptr, nullptr, prim_b, pU, nullptr, nullptr, 256, K2);

    // 3) squash + u_hat
    squash_kernel<<<(BSZ * RTS + 255) / 256, 256>>>();
    uhat_kernel<<<dim3(RTS, 8), 160>>>(W_digit);

    // 4) dynamic routing
    zero_bij_kernel<<<(RTS * NCP + 255) / 256, 256>>>();
    for (int it = 0; it < 3; it++) {
        softmax_routes_kernel<<<1, 512>>>();
        route_sv_kernel<<<BSZ, 160>>>();
        if (it < 2) route_agree_kernel<<<RTS, 256>>>();
    }

    // 5) classes / mask / decoder (dec2/dec3 convert W from fp32 on the fly)
    classes_argmax_kernel<<<1, 256>>>();
    dec1_kernel<<<BSZ, DEC1>>>(dec_w1, dec_b1);
    hmma_gemm<0, 1, 1, 2, 1><<<dim3(BSZ / 128, DEC2 / 64), 256, SMB2>>>(
        pH1h, pH1l, nullptr, nullptr, dec_w2, dec_b2, nullptr, pH2h, pH2l, DEC2, DEC1);
    hmma_gemm<0, 2, 0, 2, 1><<<dim3(BSZ / 128, RECS / 64), 256, SMB2>>>(
        pH2h, pH2l, nullptr, nullptr, dec_w3, dec_b3, out, nullptr, nullptr, RECS, DEC2);
}

// round 6
// speedup vs baseline: 3.5267x; 1.0918x over previous
#include <cuda_runtime.h>
#include <cuda_bf16.h>
#include <math.h>
#include <stdint.h>

// ---------------- problem constants ----------------
#define BSZ   256
#define H1S   12
#define P1    144
#define RTS   512
#define NCP   10
#define K1P   128
#define K2    20736
#define M1    (BSZ*P1)    // 36864
#define M2    4096
#define RECS  102400
#define DEC1  512
#define DEC2  1024
#define ZSPL  4           // split-K factor for primary caps
#define USLICE (M2 * 256)

// ---------------- scratch ----------------
__device__ __nv_bfloat16 g_A1h[M1 * K1P], g_A1l[M1 * K1P];
__device__ __nv_bfloat16 g_W1h[256 * K1P], g_W1l[256 * K1P];
__device__ __nv_bfloat16 g_C1h[M1 * 256], g_C1l[M1 * 256];
__device__ __nv_bfloat16 g_W2h[256 * K2];
__device__ float         g_Up[ZSPL * USLICE];   // split-K partials (16MB)
__device__ __nv_bfloat16 g_H1h[BSZ * DEC1], g_H1l[BSZ * DEC1];
__device__ __nv_bfloat16 g_H2h[BSZ * DEC2], g_H2l[BSZ * DEC2];
__device__ float g_X [BSZ * RTS * 8];
__device__ float g_UH[(size_t)BSZ * RTS * 160];
__device__ float g_BIJ[RTS * NCP];
__device__ float g_CIJ[RTS * NCP];
__device__ float g_V [BSZ * 160];
__device__ int   g_IDX[BSZ];

// ---------------- helpers ----------------
__device__ __forceinline__ uint32_t smem_u32(const void* p) {
    uint32_t a;
    asm("{ .reg .u64 t; cvta.to.shared.u64 t, %1; cvt.u32.u64 %0, t; }" : "=r"(a) : "l"(p));
    return a;
}
__device__ __forceinline__ void split1(float v, __nv_bfloat16& h, __nv_bfloat16& l) {
    h = __float2bfloat16(v);
    l = __float2bfloat16(v - __bfloat162float(h));
}
__device__ __forceinline__ void ldsm_x4(uint32_t addr, uint32_t* r) {
    asm volatile("ldmatrix.sync.aligned.m8n8.x4.shared.b16 {%0,%1,%2,%3}, [%4];"
        : "=r"(r[0]), "=r"(r[1]), "=r"(r[2]), "=r"(r[3]) : "r"(addr));
}
__device__ __forceinline__ void mma_bf16(float* c, const uint32_t* a, const uint32_t* b) {
    asm volatile(
        "mma.sync.aligned.m16n8k16.row.col.f32.bf16.bf16.f32 "
        "{%0,%1,%2,%3}, {%4,%5,%6,%7}, {%8,%9}, {%0,%1,%2,%3};"
        : "+f"(c[0]), "+f"(c[1]), "+f"(c[2]), "+f"(c[3])
        : "r"(a[0]), "r"(a[1]), "r"(a[2]), "r"(a[3]), "r"(b[0]), "r"(b[1]));
}
__device__ __forceinline__ uint4 pack8bf16(float4 f0, float4 f1) {
    __nv_bfloat162 p0 = __halves2bfloat162(__float2bfloat16(f0.x), __float2bfloat16(f0.y));
    __nv_bfloat162 p1 = __halves2bfloat162(__float2bfloat16(f0.z), __float2bfloat16(f0.w));
    __nv_bfloat162 p2 = __halves2bfloat162(__float2bfloat16(f1.x), __float2bfloat16(f1.y));
    __nv_bfloat162 p3 = __halves2bfloat162(__float2bfloat16(f1.z), __float2bfloat16(f1.w));
    uint4 r;
    r.x = *reinterpret_cast<uint32_t*>(&p0);
    r.y = *reinterpret_cast<uint32_t*>(&p1);
    r.z = *reinterpret_cast<uint32_t*>(&p2);
    r.w = *reinterpret_cast<uint32_t*>(&p3);
    return r;
}

// ---------------- HMMA split NT GEMM ----------------
// C[M,N] = act(A*W^T + bias).
// TERMS 3: ah*wh + ah*wl + al*wh ; TERMS 2: ah*wh + al*wh (A split, W bf16).
// WFP32 1: W supplied fp32, converted in loader.  MODE 1: implicit im2col of A from C1.
// OUT 0: fp32 C.  OUT 1: bf16 hi/lo pair outputs.
// SPLITK 1: gridDim.z slices of K; partial outputs at z*M*N; bias only on z==0.
template<int MODE, int ACT, int OUT, int TERMS, int WFP32, int SPLITK>
__global__ __launch_bounds__(256)
void hmma_gemm(const __nv_bfloat16* __restrict__ Ah, const __nv_bfloat16* __restrict__ Al,
               const __nv_bfloat16* __restrict__ Wh, const __nv_bfloat16* __restrict__ Wl,
               const float* __restrict__ Wf,
               const float* __restrict__ bias,
               float* __restrict__ Cf,
               __nv_bfloat16* __restrict__ Coh, __nv_bfloat16* __restrict__ Col,
               int N, int K)
{
    extern __shared__ char sm[];
    constexpr int AP   = 80;
    constexpr int ABYT = 128 * AP;
    constexpr int BBYT = 64 * AP;
    constexpr int NB   = (TERMS == 3) ? 2 : 1;
    constexpr int STG  = 2 * ABYT + NB * BBYT;

    const int t = threadIdx.x;
    const int m0 = blockIdx.x * 128;
    const int n0 = blockIdx.y * 64;
    const uint32_t sbase = smem_u32(sm);

    int arow[2], aseg[2], mbase[2];
#pragma unroll
    for (int i = 0; i < 2; i++) {
        int idx = t + i * 256;
        arow[i] = idx >> 2; aseg[i] = idx & 3;
        if (MODE == 1) {
            int m = m0 + arow[i]; int b = m >> 4, p = m & 15;
            mbase[i] = b * 144 + (p >> 2) * 12 + (p & 3);
        }
    }
    const int browg = t >> 2, bseg = t & 3;

    const int w = t >> 5, lane = t & 31;
    const int wm = w & 3, wn = w >> 2;
    const int lrow = (lane & 7) + ((lane >> 3) & 1) * 8;
    const int lk   = ((lane >> 4) & 1) * 8;

    float acc[2][4][4];
#pragma unroll
    for (int mt = 0; mt < 2; mt++)
#pragma unroll
        for (int nt = 0; nt < 4; nt++)
#pragma unroll
            for (int q = 0; q < 4; q++) acc[mt][nt][q] = 0.f;

    uint4 rAh[2], rAl[2], rBh, rBl;

    auto ldg_stage = [&](int k0) {
#pragma unroll
        for (int i = 0; i < 2; i++) {
            size_t off;
            if (MODE == 0) {
                off = (size_t)(m0 + arow[i]) * K + k0 + aseg[i] * 8;
            } else {
                int rr = k0 >> 8;
                int rowg = mbase[i] + (rr / 9) * 12 + (rr % 9);
                off = (size_t)rowg * 256 + (k0 & 255) + aseg[i] * 8;
            }
            rAh[i] = *(const uint4*)(Ah + off);
            rAl[i] = *(const uint4*)(Al + off);
        }
        size_t boff = (size_t)(n0 + browg) * K + k0 + bseg * 8;
        if (WFP32) {
            const float* wp = Wf + boff;
            float4 f0 = *(const float4*)wp;
            float4 f1 = *(const float4*)(wp + 4);
            rBh = pack8bf16(f0, f1);
        } else {
            rBh = *(const uint4*)(Wh + boff);
            if (TERMS == 3) rBl = *(const uint4*)(Wl + boff);
        }
    };
    auto sts_stage = [&](int buf) {
        char* p = sm + buf * STG;
#pragma unroll
        for (int i = 0; i < 2; i++) {
            *(uint4*)(p + arow[i] * AP + aseg[i] * 16) = rAh[i];
            *(uint4*)(p + ABYT + arow[i] * AP + aseg[i] * 16) = rAl[i];
        }
        *(uint4*)(p + 2 * ABYT + browg * AP + bseg * 16) = rBh;
        if (TERMS == 3)
            *(uint4*)(p + 2 * ABYT + BBYT + browg * AP + bseg * 16) = rBl;
    };
    // term-outer ordering: RAW distance between MMAs on the same accumulator = 8
    auto compute = [&](int buf) {
        uint32_t base = sbase + buf * STG;
#pragma unroll
        for (int kk = 0; kk < 32; kk += 16) {
            uint32_t a_h[2][4], a_l[2][4], b_h[2][4], b_l[2][4];
#pragma unroll
            for (int mt = 0; mt < 2; mt++) {
                uint32_t ad = base + (wm * 32 + mt * 16 + lrow) * AP + (kk + lk) * 2;
                ldsm_x4(ad, a_h[mt]);
                ldsm_x4(ad + ABYT, a_l[mt]);
            }
#pragma unroll
            for (int np = 0; np < 2; np++) {
                uint32_t bd = base + 2 * ABYT + (wn * 32 + np * 16 + lrow) * AP + (kk + lk) * 2;
                ldsm_x4(bd, b_h[np]);
                if (TERMS == 3) ldsm_x4(bd + BBYT, b_l[np]);
            }
#pragma unroll
            for (int mt = 0; mt < 2; mt++)
#pragma unroll
                for (int nt = 0; nt < 4; nt++)
                    mma_bf16(acc[mt][nt], a_h[mt], &b_h[nt >> 1][(nt & 1) * 2]);
            if (TERMS == 3) {
#pragma unroll
                for (int mt = 0; mt < 2; mt++)
#pragma unroll
                    for (int nt = 0; nt < 4; nt++)
                        mma_bf16(acc[mt][nt], a_h[mt], &b_l[nt >> 1][(nt & 1) * 2]);
            }
#pragma unroll
            for (int mt = 0; mt < 2; mt++)
#pragma unroll
                for (int nt = 0; nt < 4; nt++)
                    mma_bf16(acc[mt][nt], a_l[mt], &b_h[nt >> 1][(nt & 1) * 2]);
        }
    };

    const int S = SPLITK ? (K / 32 / ZSPL) : (K / 32);
    const int kbase = SPLITK ? blockIdx.z * (K / ZSPL) : 0;
    ldg_stage(kbase);
    sts_stage(0);
    __syncthreads();
    for (int s = 0; s < S; s++) {
        if (s + 1 < S) ldg_stage(kbase + (s + 1) * 32);
        compute(s & 1);
        if (s + 1 < S) sts_stage((s + 1) & 1);
        __syncthreads();
    }

    // ---- epilogue ----
    const size_t zoff = SPLITK ? (size_t)blockIdx.z * (size_t)(gridDim.x * 128) * N : 0;
#pragma unroll
    for (int mt = 0; mt < 2; mt++) {
#pragma unroll
        for (int nt = 0; nt < 4; nt++) {
            int row0 = m0 + wm * 32 + mt * 16 + (lane >> 2);
            int col  = n0 + wn * 32 + nt * 8 + (lane & 3) * 2;
            float b0, b1;
            if (SPLITK && blockIdx.z != 0) { b0 = 0.f; b1 = 0.f; }
            else { b0 = bias[col]; b1 = bias[col + 1]; }
#pragma unroll
            for (int half = 0; half < 2; half++) {
                int row = row0 + half * 8;
                float v0 = acc[mt][nt][half * 2 + 0] + b0;
                float v1 = acc[mt][nt][half * 2 + 1] + b1;
                if (ACT == 1) { v0 = fmaxf(v0, 0.f); v1 = fmaxf(v1, 0.f); }
                else if (ACT == 2) {
                    v0 = 1.f / (1.f + expf(-v0));
                    v1 = 1.f / (1.f + expf(-v1));
                }
                if (OUT == 0) {
                    *reinterpret_cast<float2*>(&Cf[zoff + (size_t)row * N + col]) = make_float2(v0, v1);
                } else {
                    __nv_bfloat16 h0, l0, h1, l1;
                    split1(v0, h0, l0); split1(v1, h1, l1);
                    __nv_bfloat162 hh = __halves2bfloat162(h0, h1);
                    __nv_bfloat162 ll = __halves2bfloat162(l0, l1);
                    *reinterpret_cast<__nv_bfloat162*>(&Coh[(size_t)row * N + col]) = hh;
                    *reinterpret_cast<__nv_bfloat162*>(&Col[(size_t)row * N + col]) = ll;
                }
            }
        }
    }
}

// ---------------- prep kernels ----------------
__global__ void im2col1_kernel(const float* __restrict__ data) {
    int idx = blockIdx.x * blockDim.x + threadIdx.x;
    if (idx >= M1 * K1P) return;
    int m = idx / K1P, kk = idx % K1P;
    float v = 0.f;
    if (kk < 81) {
        int b = m / P1, pos = m % P1;
        int y = pos / H1S, x = pos % H1S;
        int ky = kk / 9, kx = kk % 9;
        v = data[(size_t)b * 400 + (y + ky) * 20 + (x + kx)];
    }
    split1(v, g_A1h[idx], g_A1l[idx]);
}
__global__ void permute_w1_kernel(const float* __restrict__ conv1_w) {
    int idx = blockIdx.x * blockDim.x + threadIdx.x;
    if (idx >= 256 * K1P) return;
    int o = idx / K1P, kk = idx % K1P;
    float v = (kk < 81) ? conv1_w[o * 81 + kk] : 0.f;
    split1(v, g_W1h[idx], g_W1l[idx]);
}
// smem-transpose: coalesced read of prim_w[o][c][rr], coalesced write of W2h[o][rr*256+c]
__global__ void permute_w2_kernel(const float* __restrict__ prim_w) {
    __shared__ __nv_bfloat16 sm[K2];
    int o = blockIdx.x;
    int t = threadIdx.x;
    const float* src = prim_w + (size_t)o * K2;
    for (int idx = t; idx < K2; idx += 256)
        sm[idx] = __float2bfloat16(src[idx]);         // idx = c*81+rr order
    __syncthreads();
    __nv_bfloat16* dst = g_W2h + (size_t)o * K2;
    for (int idx = t; idx < K2; idx += 256) {
        int rr = idx >> 8, c = idx & 255;
        dst[idx] = sm[c * 81 + rr];
    }
}

// ---------------- capsule / routing kernels ----------------
// squash fuses the split-K partial reduction of g_Up
__global__ void squash_kernel() {
    int t = blockIdx.x * blockDim.x + threadIdx.x;
    if (t >= BSZ * RTS) return;
    int b = t / RTS, r = t % RTS;
    int o = r >> 1, hi = r & 1;
    const float* up = &g_Up[(size_t)(b * 16 + hi * 8) * 256 + o];
    float u[8], sn = 0.f;
#pragma unroll
    for (int i = 0; i < 8; i++) {
        float v = up[(size_t)i * 256];
#pragma unroll
        for (int z = 1; z < ZSPL; z++) v += up[(size_t)z * USLICE + (size_t)i * 256];
        u[i] = v; sn += v * v;
    }
    float sc = sn / ((1.f + sn) * sqrtf(sn));
#pragma unroll
    for (int i = 0; i < 8; i++) g_X[(size_t)t * 8 + i] = u[i] * sc;
}
__global__ void uhat_kernel(const float* __restrict__ Wd) {
    int r = blockIdx.x;
    int b0 = blockIdx.y * 32;
    int t = threadIdx.x;       // 160: t = c*16+o
    __shared__ float Wr[1280];
    __shared__ float Xr[256];
    for (int q = t; q < 1280; q += 160) Wr[q] = Wd[(size_t)r * 1280 + q];
    for (int q = t; q < 256; q += 160) {
        int b = q >> 3, i = q & 7;
        Xr[q] = g_X[(size_t)((b0 + b) * RTS + r) * 8 + i];
    }
    __syncthreads();
    for (int b = 0; b < 32; b++) {
        float acc = 0.f;
#pragma unroll
        for (int i = 0; i < 8; i++) acc = fmaf(Wr[t * 8 + i], Xr[b * 8 + i], acc);
        g_UH[(size_t)((b0 + b) * RTS + r) * 160 + t] = acc;
    }
}
__global__ void softmax_routes_kernel() {
    __shared__ float sm[RTS * NCP];
    __shared__ float mx[NCP], sum[NCP];
    int t = threadIdx.x; // 512
    for (int q = t; q < RTS * NCP; q += 512) sm[q] = g_BIJ[q];
    __syncthreads();
    if (t < NCP) {
        float m = -1e30f;
        for (int r = 0; r < RTS; r++) m = fmaxf(m, sm[r * NCP + t]);
        float s = 0.f;
        for (int r = 0; r < RTS; r++) s += expf(sm[r * NCP + t] - m);
        mx[t] = m; sum[t] = s;
    }
    __syncthreads();
    for (int q = t; q < RTS * NCP; q += 512) {
        int j = q % NCP;
        g_CIJ[q] = expf(sm[q] - mx[j]) / sum[j];
    }
}
// uniform=1: iteration 0, c = 1/512 exactly (softmax of zeros)
__global__ void route_sv_kernel(int uniform) {
    int b = blockIdx.x;   // 256
    int t = threadIdx.x;  // 160, t = j*16+o
    __shared__ float cs[RTS * NCP];
    if (!uniform) {
        for (int q = t; q < RTS * NCP; q += 160) cs[q] = g_CIJ[q];
        __syncthreads();
    }
    int j = t >> 4;
    const float* uh = &g_UH[(size_t)b * RTS * 160 + t];
    float acc = 0.f;
    if (uniform) {
        const float cu = 1.f / 512.f;
        for (int r = 0; r < RTS; r++) acc = fmaf(cu, uh[(size_t)r * 160], acc);
    } else {
        for (int r = 0; r < RTS; r++) acc = fmaf(cs[r * NCP + j], uh[(size_t)r * 160], acc);
    }
    float sq = acc * acc;
    float v = sq * acc / ((1.f + sq) * sqrtf(sq));
    g_V[b * 160 + t] = v;
}
__global__ void route_agree_kernel(int first) {
    int r = blockIdx.x;   // 512
    int b = threadIdx.x;  // 256
    __shared__ float red[256][NCP];
    const float4* up = reinterpret_cast<const float4*>(&g_UH[(size_t)(b * RTS + r) * 160]);
    const float4* vp = reinterpret_cast<const float4*>(&g_V[b * 160]);
    float dj[NCP];
#pragma unroll
    for (int j = 0; j < NCP; j++) dj[j] = 0.f;
#pragma unroll
    for (int q = 0; q < 40; q++) {
        float4 u4 = up[q], v4 = vp[q];
        int j = q >> 2;
        dj[j] += u4.x * v4.x + u4.y * v4.y + u4.z * v4.z + u4.w * v4.w;
    }
#pragma unroll
    for (int j = 0; j < NCP; j++) red[b][j] = dj[j];
    __syncthreads();
    if (b < NCP) {
        float s = 0.f;
        for (int q = 0; q < 256; q++) s += red[q][b];
        float val = s * (1.f / 256.f);
        if (first) g_BIJ[r * NCP + b] = val;
        else       g_BIJ[r * NCP + b] += val;
    }
}
__global__ void classes_argmax_kernel() {
    int b = threadIdx.x; // 256
    __shared__ float cl[256 * NCP];
    __shared__ float lz[NCP];
    for (int j = 0; j < NCP; j++) {
        float s = 0.f;
        for (int o = 0; o < 16; o++) {
            float v = g_V[b * 160 + j * 16 + o];
            s += v * v;
        }
        cl[b * NCP + j] = sqrtf(s);
    }
    __syncthreads();
    if (b < NCP) {
        float m = -1e30f;
        for (int q = 0; q < 256; q++) m = fmaxf(m, cl[q * NCP + b]);
        float s = 0.f;
        for (int q = 0; q < 256; q++) s += expf(cl[q * NCP + b] - m);
        lz[b] = m + logf(s);
    }
    __syncthreads();
    int best = 0;
    float bv = cl[b * NCP + 0] - lz[0];
    for (int j = 1; j < NCP; j++) {
        float v = cl[b * NCP + j] - lz[j];
        if (v > bv) { bv = v; best = j; }
    }
    g_IDX[b] = best;
}
__global__ void dec1_kernel(const float* __restrict__ w1, const float* __restrict__ b1) {
    int b = blockIdx.x;    // 256
    int k = threadIdx.x;   // 512
    __shared__ float vs[16];
    __shared__ int idx;
    if (k == 0) idx = g_IDX[b];
    __syncthreads();
    if (k < 16) vs[k] = g_V[b * 160 + idx * 16 + k];
    __syncthreads();
    float acc = b1[k];
    const float* wp = &w1[(size_t)k * 160 + idx * 16];
#pragma unroll
    for (int o = 0; o < 16; o++) acc = fmaf(vs[o], wp[o], acc);
    float v = fmaxf(acc, 0.f);
    split1(v, g_H1h[b * DEC1 + k], g_H1l[b * DEC1 + k]);
}

// ---------------- launch ----------------
extern "C" void kernel_launch(void* const* d_in, const int* in_sizes, int n_in,
                              void* d_out, int out_size) {
    const float* data    = (const float*)d_in[0];
    const float* conv1_w = (const float*)d_in[1];
    const float* conv1_b = (const float*)d_in[2];
    const float* prim_w  = (const float*)d_in[3];
    const float* prim_b  = (const float*)d_in[4];
    const float* W_digit = (const float*)d_in[5];
    const float* dec_w1  = (const float*)d_in[6];
    const float* dec_b1  = (const float*)d_in[7];
    const float* dec_w2  = (const float*)d_in[8];
    const float* dec_b2  = (const float*)d_in[9];
    const float* dec_w3  = (const float*)d_in[10];
    const float* dec_b3  = (const float*)d_in[11];
    float* out = (float*)d_out;

    __nv_bfloat16 *pA1h, *pA1l, *pW1h, *pW1l, *pC1h, *pC1l, *pW2h;
    __nv_bfloat16 *pH1h, *pH1l, *pH2h, *pH2l;
    float *pUp;
    cudaGetSymbolAddress((void**)&pA1h, g_A1h);  cudaGetSymbolAddress((void**)&pA1l, g_A1l);
    cudaGetSymbolAddress((void**)&pW1h, g_W1h);  cudaGetSymbolAddress((void**)&pW1l, g_W1l);
    cudaGetSymbolAddress((void**)&pC1h, g_C1h);  cudaGetSymbolAddress((void**)&pC1l, g_C1l);
    cudaGetSymbolAddress((void**)&pW2h, g_W2h);
    cudaGetSymbolAddress((void**)&pH1h, g_H1h);  cudaGetSymbolAddress((void**)&pH1l, g_H1l);
    cudaGetSymbolAddress((void**)&pH2h, g_H2h);  cudaGetSymbolAddress((void**)&pH2l, g_H2l);
    cudaGetSymbolAddress((void**)&pUp, g_Up);

    constexpr int SMB3 = 2 * (2 * 128 * 80 + 2 * 64 * 80);  // 61440
    constexpr int SMB2 = 2 * (2 * 128 * 80 + 1 * 64 * 80);  // 51200
    cudaFuncSetAttribute((const void*)hmma_gemm<0, 1, 1, 3, 0, 0>, cudaFuncAttributeMaxDynamicSharedMemorySize, SMB3);
    cudaFuncSetAttribute((const void*)hmma_gemm<1, 0, 0, 2, 0, 1>, cudaFuncAttributeMaxDynamicSharedMemorySize, SMB2);
    cudaFuncSetAttribute((const void*)hmma_gemm<0, 1, 1, 2, 1, 0>, cudaFuncAttributeMaxDynamicSharedMemorySize, SMB2);
    cudaFuncSetAttribute((const void*)hmma_gemm<0, 2, 0, 2, 1, 0>, cudaFuncAttributeMaxDynamicSharedMemorySize, SMB2);

    // weight preps
    permute_w1_kernel<<<(256 * K1P + 255) / 256, 256>>>(conv1_w);
    permute_w2_kernel<<<256, 256>>>(prim_w);

    // 1) conv1: 3-term split HMMA, relu, bf16-pair out
    im2col1_kernel<<<(M1 * K1P + 255) / 256, 256>>>(data);
    hmma_gemm<0, 1, 1, 3, 0, 0><<<dim3(M1 / 128, 256 / 64), 256, SMB3>>>(
        pA1h, pA1l, pW1h, pW1l, nullptr, conv1_b, nullptr, pC1h, pC1l, 256, K1P);

    // 2) primary caps: implicit im2col, 2-term, split-K=4 partials
    hmma_gemm<1, 0, 0, 2, 0, 1><<<dim3(M2 / 128, 256 / 64, ZSPL), 256, SMB2>>>(
        pC1h, pC1l, pW2h, nullptr, nullptr, prim_b, pUp, nullptr, nullptr, 256, K2);

    // 3) squash (fuses split-K reduce) + u_hat
    squash_kernel<<<(BSZ * RTS + 255) / 256, 256>>>();
    uhat_kernel<<<dim3(RTS, 8), 160>>>(W_digit);

    // 4) dynamic routing (it0 uses analytic uniform c = 1/512)
    route_sv_kernel<<<BSZ, 160>>>(1);
    route_agree_kernel<<<RTS, 256>>>(1);
    softmax_routes_kernel<<<1, 512>>>();
    route_sv_kernel<<<BSZ, 160>>>(0);
    route_agree_kernel<<<RTS, 256>>>(0);
    softmax_routes_kernel<<<1, 512>>>();
    route_sv_kernel<<<BSZ, 160>>>(0);

    // 5) classes / mask / decoder
    classes_argmax_kernel<<<1, 256>>>();
    dec1_kernel<<<BSZ, DEC1>>>(dec_w1, dec_b1);
    hmma_gemm<0, 1, 1, 2, 1, 0><<<dim3(BSZ / 128, DEC2 / 64), 256, SMB2>>>(
        pH1h, pH1l, nullptr, nullptr, dec_w2, dec_b2, nullptr, pH2h, pH2l, DEC2, DEC1);
    hmma_gemm<0, 2, 0, 2, 1, 0><<<dim3(BSZ / 128, RECS / 64), 256, SMB2>>>(
        pH2h, pH2l, nullptr, nullptr, dec_w3, dec_b3, out, nullptr, nullptr, RECS, DEC2);
}

// round 7
// speedup vs baseline: 5.0970x; 1.4452x over previous
#include <cuda_runtime.h>
#include <cuda_bf16.h>
#include <math.h>
#include <stdint.h>

// ---------------- problem constants ----------------
#define BSZ   256
#define H1S   12
#define P1    144
#define RTS   512
#define NCP   10
#define K1P   128
#define K2    20736
#define M1    (BSZ*P1)    // 36864
#define M2    4096
#define RECS  102400
#define DEC1  512
#define DEC2  1024
#define ZSPL  4
#define USLICE (M2 * 256)

// ---------------- scratch ----------------
__device__ __nv_bfloat16 g_A1h[M1 * K1P], g_A1l[M1 * K1P];
__device__ __nv_bfloat16 g_W1h[256 * K1P];
__device__ __nv_bfloat16 g_C1h[M1 * 256];
__device__ __nv_bfloat16 g_W2h[256 * K2];
__device__ float         g_Up[ZSPL * USLICE];
__device__ __nv_bfloat16 g_H1h[BSZ * DEC1];
__device__ __nv_bfloat16 g_H2h[BSZ * DEC2];
__device__ float g_X [BSZ * RTS * 8];
__device__ __nv_bfloat16 g_UH[(size_t)BSZ * RTS * 160];   // bf16 u_hat (42MB)
__device__ float g_BIJ[RTS * NCP];
__device__ float g_CIJ[RTS * NCP];
__device__ float g_V [BSZ * 160];
__device__ int   g_IDX[BSZ];

// ---------------- helpers ----------------
__device__ __forceinline__ uint32_t smem_u32(const void* p) {
    uint32_t a;
    asm("{ .reg .u64 t; cvta.to.shared.u64 t, %1; cvt.u32.u64 %0, t; }" : "=r"(a) : "l"(p));
    return a;
}
__device__ __forceinline__ void split1(float v, __nv_bfloat16& h, __nv_bfloat16& l) {
    h = __float2bfloat16(v);
    l = __float2bfloat16(v - __bfloat162float(h));
}
__device__ __forceinline__ void ldsm_x4(uint32_t addr, uint32_t* r) {
    asm volatile("ldmatrix.sync.aligned.m8n8.x4.shared.b16 {%0,%1,%2,%3}, [%4];"
        : "=r"(r[0]), "=r"(r[1]), "=r"(r[2]), "=r"(r[3]) : "r"(addr));
}
__device__ __forceinline__ void mma_bf16(float* c, const uint32_t* a, const uint32_t* b) {
    asm volatile(
        "mma.sync.aligned.m16n8k16.row.col.f32.bf16.bf16.f32 "
        "{%0,%1,%2,%3}, {%4,%5,%6,%7}, {%8,%9}, {%0,%1,%2,%3};"
        : "+f"(c[0]), "+f"(c[1]), "+f"(c[2]), "+f"(c[3])
        : "r"(a[0]), "r"(a[1]), "r"(a[2]), "r"(a[3]), "r"(b[0]), "r"(b[1]));
}
__device__ __forceinline__ uint4 pack8bf16(float4 f0, float4 f1) {
    __nv_bfloat162 p0 = __halves2bfloat162(__float2bfloat16(f0.x), __float2bfloat16(f0.y));
    __nv_bfloat162 p1 = __halves2bfloat162(__float2bfloat16(f0.z), __float2bfloat16(f0.w));
    __nv_bfloat162 p2 = __halves2bfloat162(__float2bfloat16(f1.x), __float2bfloat16(f1.y));
    __nv_bfloat162 p3 = __halves2bfloat162(__float2bfloat16(f1.z), __float2bfloat16(f1.w));
    uint4 r;
    r.x = *reinterpret_cast<uint32_t*>(&p0);
    r.y = *reinterpret_cast<uint32_t*>(&p1);
    r.z = *reinterpret_cast<uint32_t*>(&p2);
    r.w = *reinterpret_cast<uint32_t*>(&p3);
    return r;
}

// ---------------- HMMA NT GEMM ----------------
// TERMS 1: A bf16, W bf16 (1 MMA pass).  TERMS 2: A split (ah+al), W bf16.
// TERMS 3: A split, W split.
// WFP32 1: W fp32 -> bf16 in loader. MODE 1: implicit im2col of A from C1h.
// OUT 0: fp32. OUT 1: bf16 hi+lo. OUT 2: bf16 hi only.
// SPLITK: gridDim.z K-slices, partials at z*M*N, bias on z==0 only.
template<int MODE, int ACT, int OUT, int TERMS, int WFP32, int SPLITK>
__global__ __launch_bounds__(256)
void hmma_gemm(const __nv_bfloat16* __restrict__ Ah, const __nv_bfloat16* __restrict__ Al,
               const __nv_bfloat16* __restrict__ Wh, const __nv_bfloat16* __restrict__ Wl,
               const float* __restrict__ Wf,
               const float* __restrict__ bias,
               float* __restrict__ Cf,
               __nv_bfloat16* __restrict__ Coh, __nv_bfloat16* __restrict__ Col,
               int N, int K)
{
    extern __shared__ char sm[];
    constexpr int AP   = 80;
    constexpr int ABYT = 128 * AP;
    constexpr int BBYT = 64 * AP;
    constexpr int NA   = (TERMS >= 2) ? 2 : 1;
    constexpr int NB   = (TERMS == 3) ? 2 : 1;
    constexpr int STG  = NA * ABYT + NB * BBYT;

    const int t = threadIdx.x;
    const int m0 = blockIdx.x * 128;
    const int n0 = blockIdx.y * 64;
    const uint32_t sbase = smem_u32(sm);

    int arow[2], aseg[2], mbase[2];
#pragma unroll
    for (int i = 0; i < 2; i++) {
        int idx = t + i * 256;
        arow[i] = idx >> 2; aseg[i] = idx & 3;
        if (MODE == 1) {
            int m = m0 + arow[i]; int b = m >> 4, p = m & 15;
            mbase[i] = b * 144 + (p >> 2) * 12 + (p & 3);
        }
    }
    const int browg = t >> 2, bseg = t & 3;

    const int w = t >> 5, lane = t & 31;
    const int wm = w & 3, wn = w >> 2;
    const int lrow = (lane & 7) + ((lane >> 3) & 1) * 8;
    const int lk   = ((lane >> 4) & 1) * 8;

    float acc[2][4][4];
#pragma unroll
    for (int mt = 0; mt < 2; mt++)
#pragma unroll
        for (int nt = 0; nt < 4; nt++)
#pragma unroll
            for (int q = 0; q < 4; q++) acc[mt][nt][q] = 0.f;

    uint4 rAh[2], rAl[2], rBh, rBl;

    auto ldg_stage = [&](int k0) {
#pragma unroll
        for (int i = 0; i < 2; i++) {
            size_t off;
            if (MODE == 0) {
                off = (size_t)(m0 + arow[i]) * K + k0 + aseg[i] * 8;
            } else {
                int rr = k0 >> 8;
                int rowg = mbase[i] + (rr / 9) * 12 + (rr % 9);
                off = (size_t)rowg * 256 + (k0 & 255) + aseg[i] * 8;
            }
            rAh[i] = *(const uint4*)(Ah + off);
            if (NA == 2) rAl[i] = *(const uint4*)(Al + off);
        }
        size_t boff = (size_t)(n0 + browg) * K + k0 + bseg * 8;
        if (WFP32) {
            const float* wp = Wf + boff;
            float4 f0 = *(const float4*)wp;
            float4 f1 = *(const float4*)(wp + 4);
            rBh = pack8bf16(f0, f1);
        } else {
            rBh = *(const uint4*)(Wh + boff);
            if (TERMS == 3) rBl = *(const uint4*)(Wl + boff);
        }
    };
    auto sts_stage = [&](int buf) {
        char* p = sm + buf * STG;
#pragma unroll
        for (int i = 0; i < 2; i++) {
            *(uint4*)(p + arow[i] * AP + aseg[i] * 16) = rAh[i];
            if (NA == 2)
                *(uint4*)(p + ABYT + arow[i] * AP + aseg[i] * 16) = rAl[i];
        }
        *(uint4*)(p + NA * ABYT + browg * AP + bseg * 16) = rBh;
        if (TERMS == 3)
            *(uint4*)(p + NA * ABYT + BBYT + browg * AP + bseg * 16) = rBl;
    };
    auto compute = [&](int buf) {
        uint32_t base = sbase + buf * STG;
#pragma unroll
        for (int kk = 0; kk < 32; kk += 16) {
            uint32_t a_h[2][4], a_l[2][4], b_h[2][4], b_l[2][4];
#pragma unroll
            for (int mt = 0; mt < 2; mt++) {
                uint32_t ad = base + (wm * 32 + mt * 16 + lrow) * AP + (kk + lk) * 2;
                ldsm_x4(ad, a_h[mt]);
                if (NA == 2) ldsm_x4(ad + ABYT, a_l[mt]);
            }
#pragma unroll
            for (int np = 0; np < 2; np++) {
                uint32_t bd = base + NA * ABYT + (wn * 32 + np * 16 + lrow) * AP + (kk + lk) * 2;
                ldsm_x4(bd, b_h[np]);
                if (TERMS == 3) ldsm_x4(bd + BBYT, b_l[np]);
            }
#pragma unroll
            for (int mt = 0; mt < 2; mt++)
#pragma unroll
                for (int nt = 0; nt < 4; nt++)
                    mma_bf16(acc[mt][nt], a_h[mt], &b_h[nt >> 1][(nt & 1) * 2]);
            if (TERMS == 3) {
#pragma unroll
                for (int mt = 0; mt < 2; mt++)
#pragma unroll
                    for (int nt = 0; nt < 4; nt++)
                        mma_bf16(acc[mt][nt], a_h[mt], &b_l[nt >> 1][(nt & 1) * 2]);
            }
            if (NA == 2) {
#pragma unroll
                for (int mt = 0; mt < 2; mt++)
#pragma unroll
                    for (int nt = 0; nt < 4; nt++)
                        mma_bf16(acc[mt][nt], a_l[mt], &b_h[nt >> 1][(nt & 1) * 2]);
            }
        }
    };

    const int S = SPLITK ? (K / 32 / ZSPL) : (K / 32);
    const int kbase = SPLITK ? blockIdx.z * (K / ZSPL) : 0;
    ldg_stage(kbase);
    sts_stage(0);
    __syncthreads();
    for (int s = 0; s < S; s++) {
        if (s + 1 < S) ldg_stage(kbase + (s + 1) * 32);
        compute(s & 1);
        if (s + 1 < S) sts_stage((s + 1) & 1);
        __syncthreads();
    }

    // ---- epilogue ----
    const size_t zoff = SPLITK ? (size_t)blockIdx.z * (size_t)(gridDim.x * 128) * N : 0;
#pragma unroll
    for (int mt = 0; mt < 2; mt++) {
#pragma unroll
        for (int nt = 0; nt < 4; nt++) {
            int row0 = m0 + wm * 32 + mt * 16 + (lane >> 2);
            int col  = n0 + wn * 32 + nt * 8 + (lane & 3) * 2;
            float b0, b1;
            if (SPLITK && blockIdx.z != 0) { b0 = 0.f; b1 = 0.f; }
            else { b0 = bias[col]; b1 = bias[col + 1]; }
#pragma unroll
            for (int half = 0; half < 2; half++) {
                int row = row0 + half * 8;
                float v0 = acc[mt][nt][half * 2 + 0] + b0;
                float v1 = acc[mt][nt][half * 2 + 1] + b1;
                if (ACT == 1) { v0 = fmaxf(v0, 0.f); v1 = fmaxf(v1, 0.f); }
                else if (ACT == 2) {
                    v0 = 1.f / (1.f + expf(-v0));
                    v1 = 1.f / (1.f + expf(-v1));
                }
                if (OUT == 0) {
                    *reinterpret_cast<float2*>(&Cf[zoff + (size_t)row * N + col]) = make_float2(v0, v1);
                } else if (OUT == 1) {
                    __nv_bfloat16 h0, l0, h1, l1;
                    split1(v0, h0, l0); split1(v1, h1, l1);
                    *reinterpret_cast<__nv_bfloat162*>(&Coh[(size_t)row * N + col]) =
                        __halves2bfloat162(h0, h1);
                    *reinterpret_cast<__nv_bfloat162*>(&Col[(size_t)row * N + col]) =
                        __halves2bfloat162(l0, l1);
                } else {
                    *reinterpret_cast<__nv_bfloat162*>(&Coh[(size_t)row * N + col]) =
                        __halves2bfloat162(__float2bfloat16(v0), __float2bfloat16(v1));
                }
            }
        }
    }
}

// ---------------- prep kernels ----------------
__global__ void im2col1_kernel(const float* __restrict__ data) {
    int idx = blockIdx.x * blockDim.x + threadIdx.x;
    if (idx >= M1 * K1P) return;
    int m = idx / K1P, kk = idx % K1P;
    float v = 0.f;
    if (kk < 81) {
        int b = m / P1, pos = m % P1;
        int y = pos / H1S, x = pos % H1S;
        int ky = kk / 9, kx = kk % 9;
        v = data[(size_t)b * 400 + (y + ky) * 20 + (x + kx)];
    }
    split1(v, g_A1h[idx], g_A1l[idx]);
}
__global__ void permute_w1_kernel(const float* __restrict__ conv1_w) {
    int idx = blockIdx.x * blockDim.x + threadIdx.x;
    if (idx >= 256 * K1P) return;
    int o = idx / K1P, kk = idx % K1P;
    float v = (kk < 81) ? conv1_w[o * 81 + kk] : 0.f;
    g_W1h[idx] = __float2bfloat16(v);
}
__global__ void permute_w2_kernel(const float* __restrict__ prim_w) {
    __shared__ __nv_bfloat16 sm[K2];
    int o = blockIdx.x;
    int t = threadIdx.x;
    const float* src = prim_w + (size_t)o * K2;
    for (int idx = t; idx < K2; idx += 256)
        sm[idx] = __float2bfloat16(src[idx]);
    __syncthreads();
    __nv_bfloat16* dst = g_W2h + (size_t)o * K2;
    for (int idx = t; idx < K2; idx += 256) {
        int rr = idx >> 8, c = idx & 255;
        dst[idx] = sm[c * 81 + rr];
    }
}

// ---------------- capsule / routing kernels ----------------
__global__ void squash_kernel() {
    int t = blockIdx.x * blockDim.x + threadIdx.x;
    if (t >= BSZ * RTS) return;
    int b = t / RTS, r = t % RTS;
    int o = r >> 1, hi = r & 1;
    const float* up = &g_Up[(size_t)(b * 16 + hi * 8) * 256 + o];
    float u[8], sn = 0.f;
#pragma unroll
    for (int i = 0; i < 8; i++) {
        float v = up[(size_t)i * 256];
#pragma unroll
        for (int z = 1; z < ZSPL; z++) v += up[(size_t)z * USLICE + (size_t)i * 256];
        u[i] = v; sn += v * v;
    }
    float sc = sn / ((1.f + sn) * sqrtf(sn));
#pragma unroll
    for (int i = 0; i < 8; i++) g_X[(size_t)t * 8 + i] = u[i] * sc;
}
__global__ void uhat_kernel(const float* __restrict__ Wd) {
    int r = blockIdx.x;
    int b0 = blockIdx.y * 32;
    int t = threadIdx.x;       // 160: t = c*16+o
    __shared__ float Wr[1280];
    __shared__ float Xr[256];
    for (int q = t; q < 1280; q += 160) Wr[q] = Wd[(size_t)r * 1280 + q];
    for (int q = t; q < 256; q += 160) {
        int b = q >> 3, i = q & 7;
        Xr[q] = g_X[(size_t)((b0 + b) * RTS + r) * 8 + i];
    }
    __syncthreads();
    for (int b = 0; b < 32; b++) {
        float acc = 0.f;
#pragma unroll
        for (int i = 0; i < 8; i++) acc = fmaf(Wr[t * 8 + i], Xr[b * 8 + i], acc);
        g_UH[(size_t)((b0 + b) * RTS + r) * 160 + t] = __float2bfloat16(acc);
    }
}
__global__ void softmax_routes_kernel() {
    __shared__ float sm[RTS * NCP];
    __shared__ float mx[NCP], sum[NCP];
    int t = threadIdx.x; // 512
    for (int q = t; q < RTS * NCP; q += 512) sm[q] = g_BIJ[q];
    __syncthreads();
    if (t < NCP) {
        float m = -1e30f;
        for (int r = 0; r < RTS; r++) m = fmaxf(m, sm[r * NCP + t]);
        float s = 0.f;
        for (int r = 0; r < RTS; r++) s += expf(sm[r * NCP + t] - m);
        mx[t] = m; sum[t] = s;
    }
    __syncthreads();
    for (int q = t; q < RTS * NCP; q += 512) {
        int j = q % NCP;
        g_CIJ[q] = expf(sm[q] - mx[j]) / sum[j];
    }
}
__global__ void route_sv_kernel(int uniform) {
    int b = blockIdx.x;   // 256
    int t = threadIdx.x;  // 160, t = j*16+o
    __shared__ float cs[RTS * NCP];
    if (!uniform) {
        for (int q = t; q < RTS * NCP; q += 160) cs[q] = g_CIJ[q];
        __syncthreads();
    }
    int j = t >> 4;
    const __nv_bfloat16* uh = &g_UH[(size_t)b * RTS * 160 + t];
    float acc = 0.f;
    if (uniform) {
        const float cu = 1.f / 512.f;
        for (int r = 0; r < RTS; r++)
            acc = fmaf(cu, __bfloat162float(uh[(size_t)r * 160]), acc);
    } else {
        for (int r = 0; r < RTS; r++)
            acc = fmaf(cs[r * NCP + j], __bfloat162float(uh[(size_t)r * 160]), acc);
    }
    float sq = acc * acc;
    float v = sq * acc / ((1.f + sq) * sqrtf(sq));
    g_V[b * 160 + t] = v;
}
__global__ void route_agree_kernel(int first) {
    int r = blockIdx.x;   // 512
    int b = threadIdx.x;  // 256
    __shared__ float red[256][NCP];
    const uint4* up = reinterpret_cast<const uint4*>(&g_UH[(size_t)(b * RTS + r) * 160]);
    const float4* vp = reinterpret_cast<const float4*>(&g_V[b * 160]);
    float dj[NCP];
#pragma unroll
    for (int j = 0; j < NCP; j++) dj[j] = 0.f;
#pragma unroll
    for (int q = 0; q < 20; q++) {      // 20 uint4 x 8 bf16 = 160
        uint4 u4 = up[q];
        float4 v0 = vp[q * 2 + 0];
        float4 v1 = vp[q * 2 + 1];
        int j = q >> 1;
        float2 a0 = __bfloat1622float2(*reinterpret_cast<__nv_bfloat162*>(&u4.x));
        float2 a1 = __bfloat1622float2(*reinterpret_cast<__nv_bfloat162*>(&u4.y));
        float2 a2 = __bfloat1622float2(*reinterpret_cast<__nv_bfloat162*>(&u4.z));
        float2 a3 = __bfloat1622float2(*reinterpret_cast<__nv_bfloat162*>(&u4.w));
        dj[j] += a0.x * v0.x + a0.y * v0.y + a1.x * v0.z + a1.y * v0.w
               + a2.x * v1.x + a2.y * v1.y + a3.x * v1.z + a3.y * v1.w;
    }
#pragma unroll
    for (int j = 0; j < NCP; j++) red[b][j] = dj[j];
    __syncthreads();
    if (b < NCP) {
        float s = 0.f;
        for (int q = 0; q < 256; q++) s += red[q][b];
        float val = s * (1.f / 256.f);
        if (first) g_BIJ[r * NCP + b] = val;
        else       g_BIJ[r * NCP + b] += val;
    }
}
__global__ void classes_argmax_kernel() {
    int b = threadIdx.x; // 256
    __shared__ float cl[256 * NCP];
    __shared__ float lz[NCP];
    for (int j = 0; j < NCP; j++) {
        float s = 0.f;
        for (int o = 0; o < 16; o++) {
            float v = g_V[b * 160 + j * 16 + o];
            s += v * v;
        }
        cl[b * NCP + j] = sqrtf(s);
    }
    __syncthreads();
    if (b < NCP) {
        float m = -1e30f;
        for (int q = 0; q < 256; q++) m = fmaxf(m, cl[q * NCP + b]);
        float s = 0.f;
        for (int q = 0; q < 256; q++) s += expf(cl[q * NCP + b] - m);
        lz[b] = m + logf(s);
    }
    __syncthreads();
    int best = 0;
    float bv = cl[b * NCP + 0] - lz[0];
    for (int j = 1; j < NCP; j++) {
        float v = cl[b * NCP + j] - lz[j];
        if (v > bv) { bv = v; best = j; }
    }
    g_IDX[b] = best;
}
__global__ void dec1_kernel(const float* __restrict__ w1, const float* __restrict__ b1) {
    int b = blockIdx.x;    // 256
    int k = threadIdx.x;   // 512
    __shared__ float vs[16];
    __shared__ int idx;
    if (k == 0) idx = g_IDX[b];
    __syncthreads();
    if (k < 16) vs[k] = g_V[b * 160 + idx * 16 + k];
    __syncthreads();
    float acc = b1[k];
    const float* wp = &w1[(size_t)k * 160 + idx * 16];
#pragma unroll
    for (int o = 0; o < 16; o++) acc = fmaf(vs[o], wp[o], acc);
    g_H1h[b * DEC1 + k] = __float2bfloat16(fmaxf(acc, 0.f));
}

// ---------------- launch ----------------
extern "C" void kernel_launch(void* const* d_in, const int* in_sizes, int n_in,
                              void* d_out, int out_size) {
    const float* data    = (const float*)d_in[0];
    const float* conv1_w = (const float*)d_in[1];
    const float* conv1_b = (const float*)d_in[2];
    const float* prim_w  = (const float*)d_in[3];
    const float* prim_b  = (const float*)d_in[4];
    const float* W_digit = (const float*)d_in[5];
    const float* dec_w1  = (const float*)d_in[6];
    const float* dec_b1  = (const float*)d_in[7];
    const float* dec_w2  = (const float*)d_in[8];
    const float* dec_b2  = (const float*)d_in[9];
    const float* dec_w3  = (const float*)d_in[10];
    const float* dec_b3  = (const float*)d_in[11];
    float* out = (float*)d_out;

    __nv_bfloat16 *pA1h, *pA1l, *pW1h, *pC1h, *pW2h, *pH1h, *pH2h;
    float *pUp;
    cudaGetSymbolAddress((void**)&pA1h, g_A1h);  cudaGetSymbolAddress((void**)&pA1l, g_A1l);
    cudaGetSymbolAddress((void**)&pW1h, g_W1h);
    cudaGetSymbolAddress((void**)&pC1h, g_C1h);
    cudaGetSymbolAddress((void**)&pW2h, g_W2h);
    cudaGetSymbolAddress((void**)&pH1h, g_H1h);
    cudaGetSymbolAddress((void**)&pH2h, g_H2h);
    cudaGetSymbolAddress((void**)&pUp, g_Up);

    constexpr int SMB2 = 2 * (2 * 128 * 80 + 1 * 64 * 80);  // 51200 (TERMS=2)
    constexpr int SMB1 = 2 * (1 * 128 * 80 + 1 * 64 * 80);  // 30720 (TERMS=1)
    cudaFuncSetAttribute((const void*)hmma_gemm<0, 1, 2, 2, 0, 0>, cudaFuncAttributeMaxDynamicSharedMemorySize, SMB2);
    cudaFuncSetAttribute((const void*)hmma_gemm<1, 0, 0, 1, 0, 1>, cudaFuncAttributeMaxDynamicSharedMemorySize, SMB1);
    cudaFuncSetAttribute((const void*)hmma_gemm<0, 1, 2, 1, 1, 0>, cudaFuncAttributeMaxDynamicSharedMemorySize, SMB1);
    cudaFuncSetAttribute((const void*)hmma_gemm<0, 2, 0, 1, 1, 0>, cudaFuncAttributeMaxDynamicSharedMemorySize, SMB1);

    // weight preps
    permute_w1_kernel<<<(256 * K1P + 255) / 256, 256>>>(conv1_w);
    permute_w2_kernel<<<256, 256>>>(prim_w);

    // 1) conv1: 2-term (A split, W bf16), relu, bf16 hi-only out
    im2col1_kernel<<<(M1 * K1P + 255) / 256, 256>>>(data);
    hmma_gemm<0, 1, 2, 2, 0, 0><<<dim3(M1 / 128, 256 / 64), 256, SMB2>>>(
        pA1h, pA1l, pW1h, nullptr, nullptr, conv1_b, nullptr, pC1h, nullptr, 256, K1P);

    // 2) primary caps: implicit im2col, 1-term bf16, split-K=4 partials
    hmma_gemm<1, 0, 0, 1, 0, 1><<<dim3(M2 / 128, 256 / 64, ZSPL), 256, SMB1>>>(
        pC1h, nullptr, pW2h, nullptr, nullptr, prim_b, pUp, nullptr, nullptr, 256, K2);

    // 3) squash (fused split-K reduce) + u_hat (bf16 out)
    squash_kernel<<<(BSZ * RTS + 255) / 256, 256>>>();
    uhat_kernel<<<dim3(RTS, 8), 160>>>(W_digit);

    // 4) dynamic routing (it0 analytic uniform c)
    route_sv_kernel<<<BSZ, 160>>>(1);
    route_agree_kernel<<<RTS, 256>>>(1);
    softmax_routes_kernel<<<1, 512>>>();
    route_sv_kernel<<<BSZ, 160>>>(0);
    route_agree_kernel<<<RTS, 256>>>(0);
    softmax_routes_kernel<<<1, 512>>>();
    route_sv_kernel<<<BSZ, 160>>>(0);

    // 5) classes / mask / decoder (1-term bf16 GEMMs, W converted on the fly)
    classes_argmax_kernel<<<1, 256>>>();
    dec1_kernel<<<BSZ, DEC1>>>(dec_w1, dec_b1);
    hmma_gemm<0, 1, 2, 1, 1, 0><<<dim3(BSZ / 128, DEC2 / 64), 256, SMB1>>>(
        pH1h, nullptr, nullptr, nullptr, dec_w2, dec_b2, nullptr, pH2h, nullptr, DEC2, DEC1);
    hmma_gemm<0, 2, 0, 1, 1, 0><<<dim3(BSZ / 128, RECS / 64), 256, SMB1>>>(
        pH2h, nullptr, nullptr, nullptr, dec_w3, dec_b3, out, nullptr, nullptr, RECS, DEC2);
}

// round 8
// speedup vs baseline: 6.0810x; 1.1931x over previous
#include <cuda_runtime.h>
#include <cuda_bf16.h>
#include <math.h>
#include <stdint.h>

// ---------------- problem constants ----------------
#define BSZ   256
#define H1S   12
#define P1    144
#define RTS   512
#define NCP   10
#define K1P   128
#define K2    20736
#define M1    (BSZ*P1)    // 36864
#define M2    4096
#define RECS  102400
#define DEC1  512
#define DEC2  1024
#define ZSPL  4
#define USLICE (M2 * 256)

// ---------------- scratch ----------------
__device__ __nv_bfloat16 g_A1h[M1 * K1P];
__device__ __nv_bfloat16 g_W1h[256 * K1P];
__device__ __nv_bfloat16 g_C1h[M1 * 256];
__device__ __nv_bfloat16 g_W2h[256 * K2];
__device__ float         g_Up[ZSPL * USLICE];
__device__ __nv_bfloat16 g_H1h[BSZ * DEC1];
__device__ __nv_bfloat16 g_H2h[BSZ * DEC2];
__device__ float g_X [BSZ * RTS * 8];
__device__ __nv_bfloat16 g_UH[(size_t)BSZ * RTS * 160];
__device__ float g_BIJ[RTS * NCP];
__device__ float g_CIJ[RTS * NCP];
__device__ float g_V [BSZ * 160];
__device__ int   g_IDX[BSZ];

// ---------------- helpers ----------------
__device__ __forceinline__ uint32_t smem_u32(const void* p) {
    uint32_t a;
    asm("{ .reg .u64 t; cvta.to.shared.u64 t, %1; cvt.u32.u64 %0, t; }" : "=r"(a) : "l"(p));
    return a;
}
__device__ __forceinline__ void ldsm_x4(uint32_t addr, uint32_t* r) {
    asm volatile("ldmatrix.sync.aligned.m8n8.x4.shared.b16 {%0,%1,%2,%3}, [%4];"
        : "=r"(r[0]), "=r"(r[1]), "=r"(r[2]), "=r"(r[3]) : "r"(addr));
}
__device__ __forceinline__ void mma_bf16(float* c, const uint32_t* a, const uint32_t* b) {
    asm volatile(
        "mma.sync.aligned.m16n8k16.row.col.f32.bf16.bf16.f32 "
        "{%0,%1,%2,%3}, {%4,%5,%6,%7}, {%8,%9}, {%0,%1,%2,%3};"
        : "+f"(c[0]), "+f"(c[1]), "+f"(c[2]), "+f"(c[3])
        : "r"(a[0]), "r"(a[1]), "r"(a[2]), "r"(a[3]), "r"(b[0]), "r"(b[1]));
}
__device__ __forceinline__ uint4 pack8bf16(float4 f0, float4 f1) {
    __nv_bfloat162 p0 = __halves2bfloat162(__float2bfloat16(f0.x), __float2bfloat16(f0.y));
    __nv_bfloat162 p1 = __halves2bfloat162(__float2bfloat16(f0.z), __float2bfloat16(f0.w));
    __nv_bfloat162 p2 = __halves2bfloat162(__float2bfloat16(f1.x), __float2bfloat16(f1.y));
    __nv_bfloat162 p3 = __halves2bfloat162(__float2bfloat16(f1.z), __float2bfloat16(f1.w));
    uint4 r;
    r.x = *reinterpret_cast<uint32_t*>(&p0);
    r.y = *reinterpret_cast<uint32_t*>(&p1);
    r.z = *reinterpret_cast<uint32_t*>(&p2);
    r.w = *reinterpret_cast<uint32_t*>(&p3);
    return r;
}

// ---------------- HMMA bf16 NT GEMM, BM=128 BN=128 BK=32 ----------------
// 8 warps, warp tile 32(M) x 64(N). 6 ldmatrix per 16 MMAs per k16.
// WFP32 1: W fp32 -> bf16 in loader. MODE 1: implicit im2col of A from C1h.
// OUT 0: fp32. OUT 2: bf16. SPLITK: gridDim.z K-slices, bias on z==0 only.
template<int MODE, int ACT, int OUT, int WFP32, int SPLITK>
__global__ __launch_bounds__(256)
void hmma_gemm(const __nv_bfloat16* __restrict__ Ah,
               const __nv_bfloat16* __restrict__ Wh,
               const float* __restrict__ Wf,
               const float* __restrict__ bias,
               float* __restrict__ Cf,
               __nv_bfloat16* __restrict__ Coh,
               int N, int K)
{
    extern __shared__ char sm[];
    constexpr int AP   = 80;           // bytes per 32-bf16 row
    constexpr int ABYT = 128 * AP;     // 10240
    constexpr int BBYT = 128 * AP;     // 10240
    constexpr int STG  = ABYT + BBYT;  // 20480 / stage

    const int t = threadIdx.x;
    const int m0 = blockIdx.x * 128;
    const int n0 = blockIdx.y * 128;
    const uint32_t sbase = smem_u32(sm);

    int r4[2], s4[2], mbase[2];
#pragma unroll
    for (int i = 0; i < 2; i++) {
        int idx = t + i * 256;
        r4[i] = idx >> 2; s4[i] = idx & 3;
        if (MODE == 1) {
            int m = m0 + r4[i]; int b = m >> 4, p = m & 15;
            mbase[i] = b * 144 + (p >> 2) * 12 + (p & 3);
        }
    }

    const int w = t >> 5, lane = t & 31;
    const int wm = w >> 1, wn = w & 1;         // 4 x 2 warps
    const int lrow = (lane & 7) + ((lane >> 3) & 1) * 8;
    const int lk   = ((lane >> 4) & 1) * 8;

    float acc[2][8][4];
#pragma unroll
    for (int mt = 0; mt < 2; mt++)
#pragma unroll
        for (int nt = 0; nt < 8; nt++)
#pragma unroll
            for (int q = 0; q < 4; q++) acc[mt][nt][q] = 0.f;

    uint4 rA[2], rB[2];

    auto ldg_stage = [&](int k0) {
#pragma unroll
        for (int i = 0; i < 2; i++) {
            size_t aoff;
            if (MODE == 0) {
                aoff = (size_t)(m0 + r4[i]) * K + k0 + s4[i] * 8;
            } else {
                int rr = k0 >> 8;
                int rowg = mbase[i] + (rr / 9) * 12 + (rr % 9);
                aoff = (size_t)rowg * 256 + (k0 & 255) + s4[i] * 8;
            }
            rA[i] = *(const uint4*)(Ah + aoff);
            size_t boff = (size_t)(n0 + r4[i]) * K + k0 + s4[i] * 8;
            if (WFP32) {
                const float* wp = Wf + boff;
                rB[i] = pack8bf16(*(const float4*)wp, *(const float4*)(wp + 4));
            } else {
                rB[i] = *(const uint4*)(Wh + boff);
            }
        }
    };
    auto sts_stage = [&](int buf) {
        char* p = sm + buf * STG;
#pragma unroll
        for (int i = 0; i < 2; i++) {
            *(uint4*)(p + r4[i] * AP + s4[i] * 16) = rA[i];
            *(uint4*)(p + ABYT + r4[i] * AP + s4[i] * 16) = rB[i];
        }
    };
    auto compute = [&](int buf) {
        uint32_t base = sbase + buf * STG;
#pragma unroll
        for (int kk = 0; kk < 32; kk += 16) {
            uint32_t a_h[2][4], b_h[4][4];
#pragma unroll
            for (int mt = 0; mt < 2; mt++) {
                uint32_t ad = base + (wm * 32 + mt * 16 + lrow) * AP + (kk + lk) * 2;
                ldsm_x4(ad, a_h[mt]);
            }
#pragma unroll
            for (int np = 0; np < 4; np++) {
                uint32_t bd = base + ABYT + (wn * 64 + np * 16 + lrow) * AP + (kk + lk) * 2;
                ldsm_x4(bd, b_h[np]);
            }
#pragma unroll
            for (int mt = 0; mt < 2; mt++)
#pragma unroll
                for (int nt = 0; nt < 8; nt++)
                    mma_bf16(acc[mt][nt], a_h[mt], &b_h[nt >> 1][(nt & 1) * 2]);
        }
    };

    const int S = SPLITK ? (K / 32 / ZSPL) : (K / 32);
    const int kbase = SPLITK ? blockIdx.z * (K / ZSPL) : 0;
    ldg_stage(kbase);
    sts_stage(0);
    __syncthreads();
    for (int s = 0; s < S; s++) {
        if (s + 1 < S) ldg_stage(kbase + (s + 1) * 32);
        compute(s & 1);
        if (s + 1 < S) sts_stage((s + 1) & 1);
        __syncthreads();
    }

    // ---- epilogue ----
    const size_t zoff = SPLITK ? (size_t)blockIdx.z * (size_t)(gridDim.x * 128) * N : 0;
#pragma unroll
    for (int mt = 0; mt < 2; mt++) {
#pragma unroll
        for (int nt = 0; nt < 8; nt++) {
            int row0 = m0 + wm * 32 + mt * 16 + (lane >> 2);
            int col  = n0 + wn * 64 + nt * 8 + (lane & 3) * 2;
            float b0, b1;
            if (SPLITK && blockIdx.z != 0) { b0 = 0.f; b1 = 0.f; }
            else { b0 = bias[col]; b1 = bias[col + 1]; }
#pragma unroll
            for (int half = 0; half < 2; half++) {
                int row = row0 + half * 8;
                float v0 = acc[mt][nt][half * 2 + 0] + b0;
                float v1 = acc[mt][nt][half * 2 + 1] + b1;
                if (ACT == 1) { v0 = fmaxf(v0, 0.f); v1 = fmaxf(v1, 0.f); }
                else if (ACT == 2) {
                    v0 = 1.f / (1.f + expf(-v0));
                    v1 = 1.f / (1.f + expf(-v1));
                }
                if (OUT == 0) {
                    *reinterpret_cast<float2*>(&Cf[zoff + (size_t)row * N + col]) = make_float2(v0, v1);
                } else {
                    *reinterpret_cast<__nv_bfloat162*>(&Coh[(size_t)row * N + col]) =
                        __halves2bfloat162(__float2bfloat16(v0), __float2bfloat16(v1));
                }
            }
        }
    }
}

// ---------------- prep kernels ----------------
__global__ void im2col1_kernel(const float* __restrict__ data) {
    int idx = blockIdx.x * blockDim.x + threadIdx.x;
    if (idx >= M1 * K1P) return;
    int m = idx / K1P, kk = idx % K1P;
    float v = 0.f;
    if (kk < 81) {
        int b = m / P1, pos = m % P1;
        int y = pos / H1S, x = pos % H1S;
        int ky = kk / 9, kx = kk % 9;
        v = data[(size_t)b * 400 + (y + ky) * 20 + (x + kx)];
    }
    g_A1h[idx] = __float2bfloat16(v);
}
__global__ void permute_w1_kernel(const float* __restrict__ conv1_w) {
    int idx = blockIdx.x * blockDim.x + threadIdx.x;
    if (idx >= 256 * K1P) return;
    int o = idx / K1P, kk = idx % K1P;
    float v = (kk < 81) ? conv1_w[o * 81 + kk] : 0.f;
    g_W1h[idx] = __float2bfloat16(v);
}
__global__ void permute_w2_kernel(const float* __restrict__ prim_w) {
    __shared__ __nv_bfloat16 sm[K2];
    int o = blockIdx.x;
    int t = threadIdx.x;
    const float* src = prim_w + (size_t)o * K2;
    for (int idx = t; idx < K2; idx += 256)
        sm[idx] = __float2bfloat16(src[idx]);
    __syncthreads();
    __nv_bfloat16* dst = g_W2h + (size_t)o * K2;
    for (int idx = t; idx < K2; idx += 256) {
        int rr = idx >> 8, c = idx & 255;
        dst[idx] = sm[c * 81 + rr];
    }
}

// ---------------- capsule / routing kernels ----------------
__global__ void squash_kernel() {
    int t = blockIdx.x * blockDim.x + threadIdx.x;
    if (t >= BSZ * RTS) return;
    int b = t / RTS, r = t % RTS;
    int o = r >> 1, hi = r & 1;
    const float* up = &g_Up[(size_t)(b * 16 + hi * 8) * 256 + o];
    float u[8], sn = 0.f;
#pragma unroll
    for (int i = 0; i < 8; i++) {
        float v = up[(size_t)i * 256];
#pragma unroll
        for (int z = 1; z < ZSPL; z++) v += up[(size_t)z * USLICE + (size_t)i * 256];
        u[i] = v; sn += v * v;
    }
    float sc = sn / ((1.f + sn) * sqrtf(sn));
#pragma unroll
    for (int i = 0; i < 8; i++) g_X[(size_t)t * 8 + i] = u[i] * sc;
}
__global__ void uhat_kernel(const float* __restrict__ Wd) {
    int r = blockIdx.x;
    int b0 = blockIdx.y * 32;
    int t = threadIdx.x;       // 160: t = c*16+o
    __shared__ float Wr[1280];
    __shared__ float Xr[256];
    for (int q = t; q < 1280; q += 160) Wr[q] = Wd[(size_t)r * 1280 + q];
    for (int q = t; q < 256; q += 160) {
        int b = q >> 3, i = q & 7;
        Xr[q] = g_X[(size_t)((b0 + b) * RTS + r) * 8 + i];
    }
    __syncthreads();
    for (int b = 0; b < 32; b++) {
        float acc = 0.f;
#pragma unroll
        for (int i = 0; i < 8; i++) acc = fmaf(Wr[t * 8 + i], Xr[b * 8 + i], acc);
        g_UH[(size_t)((b0 + b) * RTS + r) * 160 + t] = __float2bfloat16(acc);
    }
}
__global__ void softmax_routes_kernel() {
    __shared__ float sm[RTS * NCP];
    __shared__ float mx[NCP], sum[NCP];
    int t = threadIdx.x; // 512
    for (int q = t; q < RTS * NCP; q += 512) sm[q] = g_BIJ[q];
    __syncthreads();
    if (t < NCP) {
        float m = -1e30f;
        for (int r = 0; r < RTS; r++) m = fmaxf(m, sm[r * NCP + t]);
        float s = 0.f;
        for (int r = 0; r < RTS; r++) s += expf(sm[r * NCP + t] - m);
        mx[t] = m; sum[t] = s;
    }
    __syncthreads();
    for (int q = t; q < RTS * NCP; q += 512) {
        int j = q % NCP;
        g_CIJ[q] = expf(sm[q] - mx[j]) / sum[j];
    }
}
__global__ void route_sv_kernel(int uniform) {
    int b = blockIdx.x;   // 256
    int t = threadIdx.x;  // 160, t = j*16+o
    __shared__ float cs[RTS * NCP];
    if (!uniform) {
        for (int q = t; q < RTS * NCP; q += 160) cs[q] = g_CIJ[q];
        __syncthreads();
    }
    int j = t >> 4;
    const __nv_bfloat16* uh = &g_UH[(size_t)b * RTS * 160 + t];
    float acc = 0.f;
    if (uniform) {
        const float cu = 1.f / 512.f;
        for (int r = 0; r < RTS; r++)
            acc = fmaf(cu, __bfloat162float(uh[(size_t)r * 160]), acc);
    } else {
        for (int r = 0; r < RTS; r++)
            acc = fmaf(cs[r * NCP + j], __bfloat162float(uh[(size_t)r * 160]), acc);
    }
    float sq = acc * acc;
    float v = sq * acc / ((1.f + sq) * sqrtf(sq));
    g_V[b * 160 + t] = v;
}
__global__ void route_agree_kernel(int first) {
    int r = blockIdx.x;   // 512
    int b = threadIdx.x;  // 256
    __shared__ float red[256][NCP];
    const uint4* up = reinterpret_cast<const uint4*>(&g_UH[(size_t)(b * RTS + r) * 160]);
    const float4* vp = reinterpret_cast<const float4*>(&g_V[b * 160]);
    float dj[NCP];
#pragma unroll
    for (int j = 0; j < NCP; j++) dj[j] = 0.f;
#pragma unroll
    for (int q = 0; q < 20; q++) {
        uint4 u4 = up[q];
        float4 v0 = vp[q * 2 + 0];
        float4 v1 = vp[q * 2 + 1];
        int j = q >> 1;
        float2 a0 = __bfloat1622float2(*reinterpret_cast<__nv_bfloat162*>(&u4.x));
        float2 a1 = __bfloat1622float2(*reinterpret_cast<__nv_bfloat162*>(&u4.y));
        float2 a2 = __bfloat1622float2(*reinterpret_cast<__nv_bfloat162*>(&u4.z));
        float2 a3 = __bfloat1622float2(*reinterpret_cast<__nv_bfloat162*>(&u4.w));
        dj[j] += a0.x * v0.x + a0.y * v0.y + a1.x * v0.z + a1.y * v0.w
               + a2.x * v1.x + a2.y * v1.y + a3.x * v1.z + a3.y * v1.w;
    }
#pragma unroll
    for (int j = 0; j < NCP; j++) red[b][j] = dj[j];
    __syncthreads();
    if (b < NCP) {
        float s = 0.f;
        for (int q = 0; q < 256; q++) s += red[q][b];
        float val = s * (1.f / 256.f);
        if (first) g_BIJ[r * NCP + b] = val;
        else       g_BIJ[r * NCP + b] += val;
    }
}
__global__ void classes_argmax_kernel() {
    int b = threadIdx.x; // 256
    __shared__ float cl[256 * NCP];
    __shared__ float lz[NCP];
    for (int j = 0; j < NCP; j++) {
        float s = 0.f;
        for (int o = 0; o < 16; o++) {
            float v = g_V[b * 160 + j * 16 + o];
            s += v * v;
        }
        cl[b * NCP + j] = sqrtf(s);
    }
    __syncthreads();
    if (b < NCP) {
        float m = -1e30f;
        for (int q = 0; q < 256; q++) m = fmaxf(m, cl[q * NCP + b]);
        float s = 0.f;
        for (int q = 0; q < 256; q++) s += expf(cl[q * NCP + b] - m);
        lz[b] = m + logf(s);
    }
    __syncthreads();
    int best = 0;
    float bv = cl[b * NCP + 0] - lz[0];
    for (int j = 1; j < NCP; j++) {
        float v = cl[b * NCP + j] - lz[j];
        if (v > bv) { bv = v; best = j; }
    }
    g_IDX[b] = best;
}
__global__ void dec1_kernel(const float* __restrict__ w1, const float* __restrict__ b1) {
    int b = blockIdx.x;    // 256
    int k = threadIdx.x;   // 512
    __shared__ float vs[16];
    __shared__ int idx;
    if (k == 0) idx = g_IDX[b];
    __syncthreads();
    if (k < 16) vs[k] = g_V[b * 160 + idx * 16 + k];
    __syncthreads();
    float acc = b1[k];
    const float* wp = &w1[(size_t)k * 160 + idx * 16];
#pragma unroll
    for (int o = 0; o < 16; o++) acc = fmaf(vs[o], wp[o], acc);
    g_H1h[b * DEC1 + k] = __float2bfloat16(fmaxf(acc, 0.f));
}

// ---------------- launch ----------------
extern "C" void kernel_launch(void* const* d_in, const int* in_sizes, int n_in,
                              void* d_out, int out_size) {
    const float* data    = (const float*)d_in[0];
    const float* conv1_w = (const float*)d_in[1];
    const float* conv1_b = (const float*)d_in[2];
    const float* prim_w  = (const float*)d_in[3];
    const float* prim_b  = (const float*)d_in[4];
    const float* W_digit = (const float*)d_in[5];
    const float* dec_w1  = (const float*)d_in[6];
    const float* dec_b1  = (const float*)d_in[7];
    const float* dec_w2  = (const float*)d_in[8];
    const float* dec_b2  = (const float*)d_in[9];
    const float* dec_w3  = (const float*)d_in[10];
    const float* dec_b3  = (const float*)d_in[11];
    float* out = (float*)d_out;

    __nv_bfloat16 *pA1h, *pW1h, *pC1h, *pW2h, *pH1h, *pH2h;
    float *pUp;
    cudaGetSymbolAddress((void**)&pA1h, g_A1h);
    cudaGetSymbolAddress((void**)&pW1h, g_W1h);
    cudaGetSymbolAddress((void**)&pC1h, g_C1h);
    cudaGetSymbolAddress((void**)&pW2h, g_W2h);
    cudaGetSymbolAddress((void**)&pH1h, g_H1h);
    cudaGetSymbolAddress((void**)&pH2h, g_H2h);
    cudaGetSymbolAddress((void**)&pUp, g_Up);

    constexpr int SMB = 2 * (128 * 80 + 128 * 80);  // 40960
    cudaFuncSetAttribute((const void*)hmma_gemm<0, 1, 2, 0, 0>, cudaFuncAttributeMaxDynamicSharedMemorySize, SMB);
    cudaFuncSetAttribute((const void*)hmma_gemm<1, 0, 0, 0, 1>, cudaFuncAttributeMaxDynamicSharedMemorySize, SMB);
    cudaFuncSetAttribute((const void*)hmma_gemm<0, 1, 2, 1, 0>, cudaFuncAttributeMaxDynamicSharedMemorySize, SMB);
    cudaFuncSetAttribute((const void*)hmma_gemm<0, 2, 0, 1, 0>, cudaFuncAttributeMaxDynamicSharedMemorySize, SMB);

    // weight preps
    permute_w1_kernel<<<(256 * K1P + 255) / 256, 256>>>(conv1_w);
    permute_w2_kernel<<<256, 256>>>(prim_w);

    // 1) conv1: bf16 HMMA, relu, bf16 out
    im2col1_kernel<<<(M1 * K1P + 255) / 256, 256>>>(data);
    hmma_gemm<0, 1, 2, 0, 0><<<dim3(M1 / 128, 256 / 128), 256, SMB>>>(
        pA1h, pW1h, nullptr, conv1_b, nullptr, pC1h, 256, K1P);

    // 2) primary caps: implicit im2col, split-K=4 partials
    hmma_gemm<1, 0, 0, 0, 1><<<dim3(M2 / 128, 256 / 128, ZSPL), 256, SMB>>>(
        pC1h, pW2h, nullptr, prim_b, pUp, nullptr, 256, K2);

    // 3) squash (fused split-K reduce) + u_hat (bf16 out)
    squash_kernel<<<(BSZ * RTS + 255) / 256, 256>>>();
    uhat_kernel<<<dim3(RTS, 8), 160>>>(W_digit);

    // 4) dynamic routing (it0 analytic uniform c)
    route_sv_kernel<<<BSZ, 160>>>(1);
    route_agree_kernel<<<RTS, 256>>>(1);
    softmax_routes_kernel<<<1, 512>>>();
    route_sv_kernel<<<BSZ, 160>>>(0);
    route_agree_kernel<<<RTS, 256>>>(0);
    softmax_routes_kernel<<<1, 512>>>();
    route_sv_kernel<<<BSZ, 160>>>(0);

    // 5) classes / mask / decoder
    classes_argmax_kernel<<<1, 256>>>();
    dec1_kernel<<<BSZ, DEC1>>>(dec_w1, dec_b1);
    hmma_gemm<0, 1, 2, 1, 0><<<dim3(BSZ / 128, DEC2 / 128), 256, SMB>>>(
        pH1h, nullptr, dec_w2, dec_b2, nullptr, pH2h, DEC2, DEC1);
    hmma_gemm<0, 2, 0, 1, 0><<<dim3(BSZ / 128, RECS / 128), 256, SMB>>>(
        pH2h, nullptr, dec_w3, dec_b3, out, nullptr, RECS, DEC2);
}

// round 9
// speedup vs baseline: 6.2682x; 1.0308x over previous
#include <cuda_runtime.h>
#include <cuda_bf16.h>
#include <math.h>
#include <stdint.h>

// ---------------- problem constants ----------------
#define BSZ   256
#define H1S   12
#define P1    144
#define RTS   512
#define NCP   10
#define K1P   128
#define K2    20736
#define M1    (BSZ*P1)    // 36864
#define M2    4096
#define RECS  102400
#define DEC1  512
#define DEC2  1024
#define ZSPL  4
#define USLICE (M2 * 256)

// ---------------- scratch ----------------
__device__ __nv_bfloat16 g_A1h[M1 * K1P];
__device__ __nv_bfloat16 g_W1h[256 * K1P];
__device__ __nv_bfloat16 g_C1h[M1 * 256];
__device__ __nv_bfloat16 g_W2h[256 * K2];
__device__ float         g_Up[ZSPL * USLICE];   // also reused as agreement partials
__device__ __nv_bfloat16 g_H1h[BSZ * DEC1];
__device__ __nv_bfloat16 g_H2h[BSZ * DEC2];
__device__ float g_X [BSZ * RTS * 8];
__device__ __nv_bfloat16 g_UH[(size_t)BSZ * RTS * 160];
__device__ float g_BIJ[RTS * NCP];
__device__ float g_CIJ[RTS * NCP];
__device__ float g_V [BSZ * 160];
__device__ int   g_IDX[BSZ];

// ---------------- helpers ----------------
__device__ __forceinline__ uint32_t smem_u32(const void* p) {
    uint32_t a;
    asm("{ .reg .u64 t; cvta.to.shared.u64 t, %1; cvt.u32.u64 %0, t; }" : "=r"(a) : "l"(p));
    return a;
}
__device__ __forceinline__ void ldsm_x4(uint32_t addr, uint32_t* r) {
    asm volatile("ldmatrix.sync.aligned.m8n8.x4.shared.b16 {%0,%1,%2,%3}, [%4];"
        : "=r"(r[0]), "=r"(r[1]), "=r"(r[2]), "=r"(r[3]) : "r"(addr));
}
__device__ __forceinline__ void mma_bf16(float* c, const uint32_t* a, const uint32_t* b) {
    asm volatile(
        "mma.sync.aligned.m16n8k16.row.col.f32.bf16.bf16.f32 "
        "{%0,%1,%2,%3}, {%4,%5,%6,%7}, {%8,%9}, {%0,%1,%2,%3};"
        : "+f"(c[0]), "+f"(c[1]), "+f"(c[2]), "+f"(c[3])
        : "r"(a[0]), "r"(a[1]), "r"(a[2]), "r"(a[3]), "r"(b[0]), "r"(b[1]));
}
__device__ __forceinline__ uint4 pack8bf16(float4 f0, float4 f1) {
    __nv_bfloat162 p0 = __halves2bfloat162(__float2bfloat16(f0.x), __float2bfloat16(f0.y));
    __nv_bfloat162 p1 = __halves2bfloat162(__float2bfloat16(f0.z), __float2bfloat16(f0.w));
    __nv_bfloat162 p2 = __halves2bfloat162(__float2bfloat16(f1.x), __float2bfloat16(f1.y));
    __nv_bfloat162 p3 = __halves2bfloat162(__float2bfloat16(f1.z), __float2bfloat16(f1.w));
    uint4 r;
    r.x = *reinterpret_cast<uint32_t*>(&p0);
    r.y = *reinterpret_cast<uint32_t*>(&p1);
    r.z = *reinterpret_cast<uint32_t*>(&p2);
    r.w = *reinterpret_cast<uint32_t*>(&p3);
    return r;
}
__device__ __forceinline__ void cp16(uint32_t d, const void* s) {
    asm volatile("cp.async.cg.shared.global [%0], [%1], 16;" :: "r"(d), "l"(s));
}
__device__ __forceinline__ void cp_commit() { asm volatile("cp.async.commit_group;"); }
template<int NW> __device__ __forceinline__ void cp_wait() {
    asm volatile("cp.async.wait_group %0;" :: "n"(NW));
}

// ============ async HMMA bf16 NT GEMM (bf16 W), BM=128 BN=128 BK=32, 3-stage ============
template<int MODE, int ACT, int OUT, int SPLITK>
__global__ __launch_bounds__(256)
void hmma_gemm_async(const __nv_bfloat16* __restrict__ Ah,
                     const __nv_bfloat16* __restrict__ Wh,
                     const float* __restrict__ bias,
                     float* __restrict__ Cf,
                     __nv_bfloat16* __restrict__ Coh,
                     int N, int K)
{
    extern __shared__ char sm[];
    constexpr int AP   = 80;
    constexpr int ABYT = 128 * AP;
    constexpr int BBYT = 128 * AP;
    constexpr int STG  = ABYT + BBYT;   // 20480

    const int t = threadIdx.x;
    const int m0 = blockIdx.x * 128;
    const int n0 = blockIdx.y * 128;
    const uint32_t sbase = smem_u32(sm);

    int r4[2], s4[2], mbase[2];
#pragma unroll
    for (int i = 0; i < 2; i++) {
        int idx = t + i * 256;
        r4[i] = idx >> 2; s4[i] = idx & 3;
        if (MODE == 1) {
            int m = m0 + r4[i]; int b = m >> 4, p = m & 15;
            mbase[i] = b * 144 + (p >> 2) * 12 + (p & 3);
        }
    }

    const int w = t >> 5, lane = t & 31;
    const int wm = w >> 1, wn = w & 1;
    const int lrow = (lane & 7) + ((lane >> 3) & 1) * 8;
    const int lk   = ((lane >> 4) & 1) * 8;

    float acc[2][8][4];
#pragma unroll
    for (int mt = 0; mt < 2; mt++)
#pragma unroll
        for (int nt = 0; nt < 8; nt++)
#pragma unroll
            for (int q = 0; q < 4; q++) acc[mt][nt][q] = 0.f;

    auto issue = [&](int s, int k0) {
        uint32_t sb = sbase + (s % 3) * STG;
#pragma unroll
        for (int i = 0; i < 2; i++) {
            size_t aoff;
            if (MODE == 0) {
                aoff = (size_t)(m0 + r4[i]) * K + k0 + s4[i] * 8;
            } else {
                int rr = k0 >> 8;
                int rowg = mbase[i] + (rr / 9) * 12 + (rr % 9);
                aoff = (size_t)rowg * 256 + (k0 & 255) + s4[i] * 8;
            }
            cp16(sb + r4[i] * AP + s4[i] * 16, Ah + aoff);
            cp16(sb + ABYT + r4[i] * AP + s4[i] * 16,
                 Wh + (size_t)(n0 + r4[i]) * K + k0 + s4[i] * 8);
        }
    };
    auto compute = [&](int buf) {
        uint32_t base = sbase + buf * STG;
#pragma unroll
        for (int kk = 0; kk < 32; kk += 16) {
            uint32_t a_h[2][4], b_h[4][4];
#pragma unroll
            for (int mt = 0; mt < 2; mt++) {
                uint32_t ad = base + (wm * 32 + mt * 16 + lrow) * AP + (kk + lk) * 2;
                ldsm_x4(ad, a_h[mt]);
            }
#pragma unroll
            for (int np = 0; np < 4; np++) {
                uint32_t bd = base + ABYT + (wn * 64 + np * 16 + lrow) * AP + (kk + lk) * 2;
                ldsm_x4(bd, b_h[np]);
            }
#pragma unroll
            for (int mt = 0; mt < 2; mt++)
#pragma unroll
                for (int nt = 0; nt < 8; nt++)
                    mma_bf16(acc[mt][nt], a_h[mt], &b_h[nt >> 1][(nt & 1) * 2]);
        }
    };

    const int S = SPLITK ? (K / 32 / ZSPL) : (K / 32);
    const int kbase = SPLITK ? blockIdx.z * (K / ZSPL) : 0;
    issue(0, kbase); cp_commit();
    issue(1, kbase + 32); cp_commit();
    for (int s = 0; s < S; s++) {
        cp_wait<1>();
        __syncthreads();
        if (s + 2 < S) issue(s + 2, kbase + (s + 2) * 32);
        cp_commit();
        compute(s % 3);
    }

    // ---- epilogue ----
    const size_t zoff = SPLITK ? (size_t)blockIdx.z * (size_t)(gridDim.x * 128) * N : 0;
#pragma unroll
    for (int mt = 0; mt < 2; mt++) {
#pragma unroll
        for (int nt = 0; nt < 8; nt++) {
            int row0 = m0 + wm * 32 + mt * 16 + (lane >> 2);
            int col  = n0 + wn * 64 + nt * 8 + (lane & 3) * 2;
            float b0, b1;
            if (SPLITK && blockIdx.z != 0) { b0 = 0.f; b1 = 0.f; }
            else { b0 = bias[col]; b1 = bias[col + 1]; }
#pragma unroll
            for (int half = 0; half < 2; half++) {
                int row = row0 + half * 8;
                float v0 = acc[mt][nt][half * 2 + 0] + b0;
                float v1 = acc[mt][nt][half * 2 + 1] + b1;
                if (ACT == 1) { v0 = fmaxf(v0, 0.f); v1 = fmaxf(v1, 0.f); }
                if (OUT == 0) {
                    *reinterpret_cast<float2*>(&Cf[zoff + (size_t)row * N + col]) = make_float2(v0, v1);
                } else {
                    *reinterpret_cast<__nv_bfloat162*>(&Coh[(size_t)row * N + col]) =
                        __halves2bfloat162(__float2bfloat16(v0), __float2bfloat16(v1));
                }
            }
        }
    }
}

// ============ 2-stage HMMA GEMM with fp32-W in-loader convert (dec2/dec3) ============
template<int ACT, int OUT>
__global__ __launch_bounds__(256)
void hmma_gemm_wf(const __nv_bfloat16* __restrict__ Ah,
                  const float* __restrict__ Wf,
                  const float* __restrict__ bias,
                  float* __restrict__ Cf,
                  __nv_bfloat16* __restrict__ Coh,
                  int N, int K)
{
    extern __shared__ char sm[];
    constexpr int AP   = 80;
    constexpr int ABYT = 128 * AP;
    constexpr int BBYT = 128 * AP;
    constexpr int STG  = ABYT + BBYT;

    const int t = threadIdx.x;
    const int m0 = blockIdx.x * 128;
    const int n0 = blockIdx.y * 128;
    const uint32_t sbase = smem_u32(sm);

    int r4[2], s4[2];
#pragma unroll
    for (int i = 0; i < 2; i++) {
        int idx = t + i * 256;
        r4[i] = idx >> 2; s4[i] = idx & 3;
    }
    const int w = t >> 5, lane = t & 31;
    const int wm = w >> 1, wn = w & 1;
    const int lrow = (lane & 7) + ((lane >> 3) & 1) * 8;
    const int lk   = ((lane >> 4) & 1) * 8;

    float acc[2][8][4];
#pragma unroll
    for (int mt = 0; mt < 2; mt++)
#pragma unroll
        for (int nt = 0; nt < 8; nt++)
#pragma unroll
            for (int q = 0; q < 4; q++) acc[mt][nt][q] = 0.f;

    uint4 rA[2], rB[2];
    auto ldg_stage = [&](int k0) {
#pragma unroll
        for (int i = 0; i < 2; i++) {
            rA[i] = *(const uint4*)(Ah + (size_t)(m0 + r4[i]) * K + k0 + s4[i] * 8);
            const float* wp = Wf + (size_t)(n0 + r4[i]) * K + k0 + s4[i] * 8;
            rB[i] = pack8bf16(*(const float4*)wp, *(const float4*)(wp + 4));
        }
    };
    auto sts_stage = [&](int buf) {
        char* p = sm + buf * STG;
#pragma unroll
        for (int i = 0; i < 2; i++) {
            *(uint4*)(p + r4[i] * AP + s4[i] * 16) = rA[i];
            *(uint4*)(p + ABYT + r4[i] * AP + s4[i] * 16) = rB[i];
        }
    };
    auto compute = [&](int buf) {
        uint32_t base = sbase + buf * STG;
#pragma unroll
        for (int kk = 0; kk < 32; kk += 16) {
            uint32_t a_h[2][4], b_h[4][4];
#pragma unroll
            for (int mt = 0; mt < 2; mt++) {
                uint32_t ad = base + (wm * 32 + mt * 16 + lrow) * AP + (kk + lk) * 2;
                ldsm_x4(ad, a_h[mt]);
            }
#pragma unroll
            for (int np = 0; np < 4; np++) {
                uint32_t bd = base + ABYT + (wn * 64 + np * 16 + lrow) * AP + (kk + lk) * 2;
                ldsm_x4(bd, b_h[np]);
            }
#pragma unroll
            for (int mt = 0; mt < 2; mt++)
#pragma unroll
                for (int nt = 0; nt < 8; nt++)
                    mma_bf16(acc[mt][nt], a_h[mt], &b_h[nt >> 1][(nt & 1) * 2]);
        }
    };

    const int S = K / 32;
    ldg_stage(0);
    sts_stage(0);
    __syncthreads();
    for (int s = 0; s < S; s++) {
        if (s + 1 < S) ldg_stage((s + 1) * 32);
        compute(s & 1);
        if (s + 1 < S) sts_stage((s + 1) & 1);
        __syncthreads();
    }

#pragma unroll
    for (int mt = 0; mt < 2; mt++) {
#pragma unroll
        for (int nt = 0; nt < 8; nt++) {
            int row0 = m0 + wm * 32 + mt * 16 + (lane >> 2);
            int col  = n0 + wn * 64 + nt * 8 + (lane & 3) * 2;
            float b0 = bias[col], b1 = bias[col + 1];
#pragma unroll
            for (int half = 0; half < 2; half++) {
                int row = row0 + half * 8;
                float v0 = acc[mt][nt][half * 2 + 0] + b0;
                float v1 = acc[mt][nt][half * 2 + 1] + b1;
                if (ACT == 1) { v0 = fmaxf(v0, 0.f); v1 = fmaxf(v1, 0.f); }
                else if (ACT == 2) {
                    v0 = 1.f / (1.f + expf(-v0));
                    v1 = 1.f / (1.f + expf(-v1));
                }
                if (OUT == 0) {
                    *reinterpret_cast<float2*>(&Cf[(size_t)row * N + col]) = make_float2(v0, v1);
                } else {
                    *reinterpret_cast<__nv_bfloat162*>(&Coh[(size_t)row * N + col]) =
                        __halves2bfloat162(__float2bfloat16(v0), __float2bfloat16(v1));
                }
            }
        }
    }
}

// ---------------- prep kernels ----------------
__global__ void im2col1_kernel(const float* __restrict__ data) {
    int idx = blockIdx.x * blockDim.x + threadIdx.x;
    if (idx >= M1 * K1P) return;
    int m = idx / K1P, kk = idx % K1P;
    float v = 0.f;
    if (kk < 81) {
        int b = m / P1, pos = m % P1;
        int y = pos / H1S, x = pos % H1S;
        int ky = kk / 9, kx = kk % 9;
        v = data[(size_t)b * 400 + (y + ky) * 20 + (x + kx)];
    }
    g_A1h[idx] = __float2bfloat16(v);
}
__global__ void permute_w1_kernel(const float* __restrict__ conv1_w) {
    int idx = blockIdx.x * blockDim.x + threadIdx.x;
    if (idx >= 256 * K1P) return;
    int o = idx / K1P, kk = idx % K1P;
    float v = (kk < 81) ? conv1_w[o * 81 + kk] : 0.f;
    g_W1h[idx] = __float2bfloat16(v);
}
__global__ void permute_w2_kernel(const float* __restrict__ prim_w) {
    __shared__ __nv_bfloat16 sm[K2];
    int o = blockIdx.x;
    int t = threadIdx.x;
    const float* src = prim_w + (size_t)o * K2;
    for (int idx = t; idx < K2; idx += 256)
        sm[idx] = __float2bfloat16(src[idx]);
    __syncthreads();
    __nv_bfloat16* dst = g_W2h + (size_t)o * K2;
    for (int idx = t; idx < K2; idx += 256) {
        int rr = idx >> 8, c = idx & 255;
        dst[idx] = sm[c * 81 + rr];
    }
}

// ---------------- capsule / routing kernels ----------------
__global__ void squash_kernel() {
    int t = blockIdx.x * blockDim.x + threadIdx.x;
    if (t >= BSZ * RTS) return;
    int b = t / RTS, r = t % RTS;
    int o = r >> 1, hi = r & 1;
    const float* up = &g_Up[(size_t)(b * 16 + hi * 8) * 256 + o];
    float u[8], sn = 0.f;
#pragma unroll
    for (int i = 0; i < 8; i++) {
        float v = up[(size_t)i * 256];
#pragma unroll
        for (int z = 1; z < ZSPL; z++) v += up[(size_t)z * USLICE + (size_t)i * 256];
        u[i] = v; sn += v * v;
    }
    float sc = sn / ((1.f + sn) * sqrtf(sn));
#pragma unroll
    for (int i = 0; i < 8; i++) g_X[(size_t)t * 8 + i] = u[i] * sc;
}
__global__ void uhat_kernel(const float* __restrict__ Wd) {
    int r = blockIdx.x;
    int b0 = blockIdx.y * 32;
    int t = threadIdx.x;       // 160: t = c*16+o
    __shared__ float Wr[1280];
    __shared__ float Xr[256];
    for (int q = t; q < 1280; q += 160) Wr[q] = Wd[(size_t)r * 1280 + q];
    for (int q = t; q < 256; q += 160) {
        int b = q >> 3, i = q & 7;
        Xr[q] = g_X[(size_t)((b0 + b) * RTS + r) * 8 + i];
    }
    __syncthreads();
    for (int b = 0; b < 32; b++) {
        float acc = 0.f;
#pragma unroll
        for (int i = 0; i < 8; i++) acc = fmaf(Wr[t * 8 + i], Xr[b * 8 + i], acc);
        g_UH[(size_t)((b0 + b) * RTS + r) * 160 + t] = __float2bfloat16(acc);
    }
}
__global__ void softmax_routes_kernel() {
    __shared__ float sm[RTS * NCP];
    __shared__ float mx[NCP], sum[NCP];
    int t = threadIdx.x; // 512
    for (int q = t; q < RTS * NCP; q += 512) sm[q] = g_BIJ[q];
    __syncthreads();
    if (t < NCP) {
        float m = -1e30f;
        for (int r = 0; r < RTS; r++) m = fmaxf(m, sm[r * NCP + t]);
        float s = 0.f;
        for (int r = 0; r < RTS; r++) s += expf(sm[r * NCP + t] - m);
        mx[t] = m; sum[t] = s;
    }
    __syncthreads();
    for (int q = t; q < RTS * NCP; q += 512) {
        int j = q % NCP;
        g_CIJ[q] = expf(sm[q] - mx[j]) / sum[j];
    }
}

// ---- fused routing: one block per b, u_hat[b] smem-resident (pitch 81 words) ----
template<int UNIFORM, int AGREE, int WRITEV>
__global__ __launch_bounds__(512)
void route_fused_kernel(float* __restrict__ agp) {
    extern __shared__ float smr[];               // [512*81] UH words, then cs
    float* cs = smr + 512 * 81;
    __shared__ float v_s[160];
    const int b = blockIdx.x;
    const int t = threadIdx.x;

    const uint32_t* src = reinterpret_cast<const uint32_t*>(&g_UH[(size_t)b * RTS * 160]);
    uint32_t* uw = reinterpret_cast<uint32_t*>(smr);
    for (int q = t; q < RTS * 80; q += 512) {
        int r = q / 80, ww = q - r * 80;
        uw[r * 81 + ww] = src[q];
    }
    if (!UNIFORM)
        for (int q = t; q < RTS * NCP; q += 512) cs[q] = g_CIJ[q];
    __syncthreads();

    if (t < 160) {
        int j = t >> 4;
        int wdx = t >> 1, hi = t & 1;
        float acc = 0.f;
        for (int r = 0; r < RTS; r++) {
            uint32_t u2 = uw[r * 81 + wdx];
            float2 a = __bfloat1622float2(*reinterpret_cast<__nv_bfloat162*>(&u2));
            float u = hi ? a.y : a.x;
            float c = UNIFORM ? (1.f / 512.f) : cs[r * NCP + j];
            acc = fmaf(c, u, acc);
        }
        float sq = acc * acc;
        float v = sq * acc / ((1.f + sq) * sqrtf(sq));
        v_s[t] = v;
        if (WRITEV) g_V[b * 160 + t] = v;
    }
    __syncthreads();

    if (AGREE) {
        int r = t;   // 512 threads = 512 routes
        const uint32_t* row = uw + r * 81;
#pragma unroll
        for (int j = 0; j < NCP; j++) {
            float d = 0.f;
#pragma unroll
            for (int ww = 0; ww < 8; ww++) {
                uint32_t u2 = row[j * 8 + ww];
                float2 a = __bfloat1622float2(*reinterpret_cast<__nv_bfloat162*>(&u2));
                d += a.x * v_s[j * 16 + ww * 2] + a.y * v_s[j * 16 + ww * 2 + 1];
            }
            agp[(size_t)b * 5120 + j * 512 + r] = d;
        }
    }
}
__global__ void route_reduce_kernel(const float* __restrict__ agp, int first) {
    int q = blockIdx.x * 512 + threadIdx.x;   // 5120
    float s = 0.f;
    for (int b = 0; b < BSZ; b++) s += agp[(size_t)b * 5120 + q];
    int j = q >> 9, r = q & 511;
    float val = s * (1.f / 256.f);
    if (first) g_BIJ[r * NCP + j] = val;
    else       g_BIJ[r * NCP + j] += val;
}

__global__ void classes_argmax_kernel() {
    int b = threadIdx.x; // 256
    __shared__ float cl[256 * NCP];
    __shared__ float lz[NCP];
    for (int j = 0; j < NCP; j++) {
        float s = 0.f;
        for (int o = 0; o < 16; o++) {
            float v = g_V[b * 160 + j * 16 + o];
            s += v * v;
        }
        cl[b * NCP + j] = sqrtf(s);
    }
    __syncthreads();
    if (b < NCP) {
        float m = -1e30f;
        for (int q = 0; q < 256; q++) m = fmaxf(m, cl[q * NCP + b]);
        float s = 0.f;
        for (int q = 0; q < 256; q++) s += expf(cl[q * NCP + b] - m);
        lz[b] = m + logf(s);
    }
    __syncthreads();
    int best = 0;
    float bv = cl[b * NCP + 0] - lz[0];
    for (int j = 1; j < NCP; j++) {
        float v = cl[b * NCP + j] - lz[j];
        if (v > bv) { bv = v; best = j; }
    }
    g_IDX[b] = best;
}
__global__ void dec1_kernel(const float* __restrict__ w1, const float* __restrict__ b1) {
    int b = blockIdx.x;    // 256
    int k = threadIdx.x;   // 512
    __shared__ float vs[16];
    __shared__ int idx;
    if (k == 0) idx = g_IDX[b];
    __syncthreads();
    if (k < 16) vs[k] = g_V[b * 160 + idx * 16 + k];
    __syncthreads();
    float acc = b1[k];
    const float* wp = &w1[(size_t)k * 160 + idx * 16];
#pragma unroll
    for (int o = 0; o < 16; o++) acc = fmaf(vs[o], wp[o], acc);
    g_H1h[b * DEC1 + k] = __float2bfloat16(fmaxf(acc, 0.f));
}

// ---------------- launch ----------------
extern "C" void kernel_launch(void* const* d_in, const int* in_sizes, int n_in,
                              void* d_out, int out_size) {
    const float* data    = (const float*)d_in[0];
    const float* conv1_w = (const float*)d_in[1];
    const float* conv1_b = (const float*)d_in[2];
    const float* prim_w  = (const float*)d_in[3];
    const float* prim_b  = (const float*)d_in[4];
    const float* W_digit = (const float*)d_in[5];
    const float* dec_w1  = (const float*)d_in[6];
    const float* dec_b1  = (const float*)d_in[7];
    const float* dec_w2  = (const float*)d_in[8];
    const float* dec_b2  = (const float*)d_in[9];
    const float* dec_w3  = (const float*)d_in[10];
    const float* dec_b3  = (const float*)d_in[11];
    float* out = (float*)d_out;

    __nv_bfloat16 *pA1h, *pW1h, *pC1h, *pW2h, *pH1h, *pH2h;
    float *pUp;
    cudaGetSymbolAddress((void**)&pA1h, g_A1h);
    cudaGetSymbolAddress((void**)&pW1h, g_W1h);
    cudaGetSymbolAddress((void**)&pC1h, g_C1h);
    cudaGetSymbolAddress((void**)&pW2h, g_W2h);
    cudaGetSymbolAddress((void**)&pH1h, g_H1h);
    cudaGetSymbolAddress((void**)&pH2h, g_H2h);
    cudaGetSymbolAddress((void**)&pUp, g_Up);

    constexpr int SMA = 3 * 20480;                  // async 3-stage
    constexpr int SMB = 2 * 20480;                  // wf 2-stage
    constexpr int SMR = 512 * 81 * 4 + 5120 * 4;    // 186368: fused routing
    cudaFuncSetAttribute((const void*)hmma_gemm_async<0, 1, 2, 0>, cudaFuncAttributeMaxDynamicSharedMemorySize, SMA);
    cudaFuncSetAttribute((const void*)hmma_gemm_async<1, 0, 0, 1>, cudaFuncAttributeMaxDynamicSharedMemorySize, SMA);
    cudaFuncSetAttribute((const void*)hmma_gemm_wf<1, 2>, cudaFuncAttributeMaxDynamicSharedMemorySize, SMB);
    cudaFuncSetAttribute((const void*)hmma_gemm_wf<2, 0>, cudaFuncAttributeMaxDynamicSharedMemorySize, SMB);
    cudaFuncSetAttribute((const void*)route_fused_kernel<1, 1, 0>, cudaFuncAttributeMaxDynamicSharedMemorySize, SMR);
    cudaFuncSetAttribute((const void*)route_fused_kernel<0, 1, 0>, cudaFuncAttributeMaxDynamicSharedMemorySize, SMR);
    cudaFuncSetAttribute((const void*)route_fused_kernel<0, 0, 1>, cudaFuncAttributeMaxDynamicSharedMemorySize, SMR);

    // weight preps
    permute_w1_kernel<<<(256 * K1P + 255) / 256, 256>>>(conv1_w);
    permute_w2_kernel<<<256, 256>>>(prim_w);

    // 1) conv1: async bf16 HMMA, relu, bf16 out
    im2col1_kernel<<<(M1 * K1P + 255) / 256, 256>>>(data);
    hmma_gemm_async<0, 1, 2, 0><<<dim3(M1 / 128, 256 / 128), 256, SMA>>>(
        pA1h, pW1h, conv1_b, nullptr, pC1h, 256, K1P);

    // 2) primary caps: implicit im2col async, split-K=4 partials
    hmma_gemm_async<1, 0, 0, 1><<<dim3(M2 / 128, 256 / 128, ZSPL), 256, SMA>>>(
        pC1h, pW2h, prim_b, pUp, nullptr, 256, K2);

    // 3) squash (fused split-K reduce) + u_hat (bf16 out)
    squash_kernel<<<(BSZ * RTS + 255) / 256, 256>>>();
    uhat_kernel<<<dim3(RTS, 8), 160>>>(W_digit);

    // 4) fused dynamic routing (u_hat smem-resident; agp reuses g_Up)
    route_fused_kernel<1, 1, 0><<<BSZ, 512, SMR>>>(pUp);
    route_reduce_kernel<<<10, 512>>>(pUp, 1);
    softmax_routes_kernel<<<1, 512>>>();
    route_fused_kernel<0, 1, 0><<<BSZ, 512, SMR>>>(pUp);
    route_reduce_kernel<<<10, 512>>>(pUp, 0);
    softmax_routes_kernel<<<1, 512>>>();
    route_fused_kernel<0, 0, 1><<<BSZ, 512, SMR>>>(pUp);

    // 5) classes / mask / decoder
    classes_argmax_kernel<<<1, 256>>>();
    dec1_kernel<<<BSZ, DEC1>>>(dec_w1, dec_b1);
    hmma_gemm_wf<1, 2><<<dim3(BSZ / 128, DEC2 / 128), 256, SMB>>>(
        pH1h, dec_w2, dec_b2, nullptr, pH2h, DEC2, DEC1);
    hmma_gemm_wf<2, 0><<<dim3(BSZ / 128, RECS / 128), 256, SMB>>>(
        pH2h, dec_w3, dec_b3, out, nullptr, RECS, DEC2);
}